// round 7
// baseline (speedup 1.0000x reference)
#include <cuda_runtime.h>
#include <cuda_bf16.h>
#include <cstdint>
#include <math.h>

#define BB 4
#define SQ 4096
#define DH 1024
#define MTOT (BB * SQ)   // 16384

typedef __nv_bfloat16  bf16;
typedef __nv_bfloat162 bf162;

// ---------------- scratch planes (hi/lo bf16 split) ----------------
__device__ bf16 g_Xh[(size_t)MTOT * DH], g_Xl[(size_t)MTOT * DH];
__device__ bf16 g_Wqh[(size_t)DH * DH], g_Wql[(size_t)DH * DH];
__device__ bf16 g_Wkh[(size_t)DH * DH], g_Wkl[(size_t)DH * DH];
__device__ bf16 g_Wvh[(size_t)DH * DH], g_Wvl[(size_t)DH * DH];
__device__ bf16 g_Qh[(size_t)MTOT * DH], g_Ql[(size_t)MTOT * DH];
__device__ bf16 g_Kh[(size_t)MTOT * DH], g_Kl[(size_t)MTOT * DH];
__device__ float g_V[(size_t)MTOT * DH];
__device__ bf16 g_Vth[(size_t)MTOT * DH], g_Vtl[(size_t)MTOT * DH];
__device__ float g_P[(size_t)BB * SQ * SQ];
__device__ bf16 g_Ph[(size_t)BB * SQ * SQ], g_Pl[(size_t)BB * SQ * SQ];

// ---------------- PTX helpers ----------------
__device__ __forceinline__ uint32_t smem_u32(const void* p) {
    uint32_t a;
    asm("{ .reg .u64 t; cvta.to.shared.u64 t, %1; cvt.u32.u64 %0, t; }" : "=r"(a) : "l"(p));
    return a;
}
__device__ __forceinline__ void cp16(uint32_t dst, const void* src) {
    asm volatile("cp.async.cg.shared.global [%0], [%1], 16;" :: "r"(dst), "l"(src));
}
#define CP_COMMIT() asm volatile("cp.async.commit_group;" ::: "memory")
#define CP_WAIT1()  asm volatile("cp.async.wait_group 1;" ::: "memory")

__device__ __forceinline__ void ldm4(uint32_t* r, uint32_t a) {
    asm volatile("ldmatrix.sync.aligned.m8n8.x4.shared.b16 {%0,%1,%2,%3}, [%4];"
                 : "=r"(r[0]), "=r"(r[1]), "=r"(r[2]), "=r"(r[3]) : "r"(a));
}
__device__ __forceinline__ void mma16816(float* d, const uint32_t* a, const uint32_t* b) {
    asm volatile("mma.sync.aligned.m16n8k16.row.col.f32.bf16.bf16.f32 "
                 "{%0,%1,%2,%3}, {%4,%5,%6,%7}, {%8,%9}, {%0,%1,%2,%3};"
                 : "+f"(d[0]), "+f"(d[1]), "+f"(d[2]), "+f"(d[3])
                 : "r"(a[0]), "r"(a[1]), "r"(a[2]), "r"(a[3]), "r"(b[0]), "r"(b[1]));
}

// ---------------- GEMM config ----------------
// C[m,n] = sum_k A[m,k]*B[n,k]; bf16 hi/lo planes, K-major; 3 MMA passes.
// CTA tile 256x128x32; 256 threads (8 warps, 4 x 2); warp tile 64x64.
#define STAGES 3
#define ROWB 80                     // 32 bf16 = 64B + 16B pad
#define SA_H 0
#define SA_L (256 * ROWB)           // 20480
#define SB_H (2 * 256 * ROWB)       // 40960
#define SB_L (SB_H + 128 * ROWB)    // 51200
#define STAGEB (SB_L + 128 * ROWB)  // 61440
#define SMEM_GEMM (STAGES * STAGEB) // 184320

__global__ void __launch_bounds__(256, 1) gemm_bf16_3p(
    const bf16* __restrict__ Ah, const bf16* __restrict__ Al,
    const bf16* __restrict__ Bh, const bf16* __restrict__ Bl,
    float* __restrict__ Cf, bf16* __restrict__ Ch, bf16* __restrict__ Cl,
    int K, int ldc, size_t sA, size_t sB, size_t sC)
{
    extern __shared__ char smem[];
    const uint32_t sb = smem_u32(smem);
    const int tid = threadIdx.x;
    const int wid = tid >> 5, lane = tid & 31;
    const int wm = wid >> 1, wn = wid & 1;     // 4 x 2 warps, warp tile 64x64

    const size_t aoff = (size_t)blockIdx.z * sA + (size_t)(blockIdx.y * 256) * K;
    const size_t boff = (size_t)blockIdx.z * sB + (size_t)(blockIdx.x * 128) * K;
    const bf16* Abh = Ah + aoff;
    const bf16* Abl = Al + aoff;
    const bf16* Bbh = Bh + boff;
    const bf16* Bbl = Bl + boff;

    float acc[4][8][4];
#pragma unroll
    for (int i = 0; i < 4; i++)
#pragma unroll
        for (int j = 0; j < 8; j++)
#pragma unroll
            for (int q = 0; q < 4; q++) acc[i][j][q] = 0.f;

    const int nch = K / 32;

    // cp.async indices: A plane 256x(4x16B); B plane 128x(4x16B)
    const int ra = tid >> 2, ca = tid & 3;          // A: 4 iters of 64 rows
    const int rb = tid >> 2, cb = tid & 3;          // B: 2 iters of 64 rows

    // ldmatrix lane addressing
    const int rA = lane & 15, cA = (lane >> 4) * 8;             // A x4
    const int rB = ((lane >> 4) * 8) + (lane & 7);              // B x4 (2 n-frags)
    const int cBk = ((lane >> 3) & 1) * 8;

#define LOAD_CHUNK(stg, ko)                                                      \
    do {                                                                         \
        uint32_t d0 = sb + (stg) * STAGEB;                                       \
        int kk = (ko) * 32;                                                      \
        _Pragma("unroll")                                                        \
        for (int i = 0; i < 4; i++) {                                            \
            int r = ra + i * 64;                                                 \
            uint32_t d = d0 + r * ROWB + ca * 16;                                \
            const bf16* sh = Abh + (size_t)r * K + kk + ca * 8;                  \
            const bf16* sl = Abl + (size_t)r * K + kk + ca * 8;                  \
            cp16(d + SA_H, sh);                                                  \
            cp16(d + SA_L, sl);                                                  \
        }                                                                        \
        _Pragma("unroll")                                                        \
        for (int i = 0; i < 2; i++) {                                            \
            int r = rb + i * 64;                                                 \
            uint32_t d = d0 + r * ROWB + cb * 16;                                \
            const bf16* sh = Bbh + (size_t)r * K + kk + cb * 8;                  \
            const bf16* sl = Bbl + (size_t)r * K + kk + cb * 8;                  \
            cp16(d + SB_H, sh);                                                  \
            cp16(d + SB_L, sl);                                                  \
        }                                                                        \
    } while (0)

#pragma unroll
    for (int s = 0; s < STAGES - 1; s++) {
        LOAD_CHUNK(s, s);
        CP_COMMIT();
    }

    for (int ch = 0; ch < nch; ch++) {
        CP_WAIT1();
        __syncthreads();

        int nx = ch + STAGES - 1;
        if (nx < nch) LOAD_CHUNK(nx % STAGES, nx);
        CP_COMMIT();

        const uint32_t st = sb + (ch % STAGES) * STAGEB;
        const uint32_t pAh = st + SA_H + (wm * 64 + rA) * ROWB + cA * 2;
        const uint32_t pAl = st + SA_L + (wm * 64 + rA) * ROWB + cA * 2;
        const uint32_t pBh = st + SB_H + (wn * 64 + rB) * ROWB + cBk * 2;
        const uint32_t pBl = st + SB_L + (wn * 64 + rB) * ROWB + cBk * 2;

#pragma unroll
        for (int ks = 0; ks < 2; ks++) {
            const uint32_t ko = ks * 32;   // 16 bf16 = 32B
            uint32_t ah[4][4], al[4][4], bh[4][4], bl[4][4];
#pragma unroll
            for (int mf = 0; mf < 4; mf++) {
                ldm4(ah[mf], pAh + mf * (16 * ROWB) + ko);
                ldm4(al[mf], pAl + mf * (16 * ROWB) + ko);
            }
#pragma unroll
            for (int j = 0; j < 4; j++) {
                ldm4(bh[j], pBh + j * (16 * ROWB) + ko);
                ldm4(bl[j], pBl + j * (16 * ROWB) + ko);
            }
#pragma unroll
            for (int mf = 0; mf < 4; mf++)
#pragma unroll
                for (int j = 0; j < 4; j++) {
                    mma16816(acc[mf][2 * j],     ah[mf], &bh[j][0]);   // hi*hi (n..n+7)
                    mma16816(acc[mf][2 * j + 1], ah[mf], &bh[j][2]);   // hi*hi (n+8..n+15)
                    mma16816(acc[mf][2 * j],     ah[mf], &bl[j][0]);   // hi*lo
                    mma16816(acc[mf][2 * j + 1], ah[mf], &bl[j][2]);
                    mma16816(acc[mf][2 * j],     al[mf], &bh[j][0]);   // lo*hi
                    mma16816(acc[mf][2 * j + 1], al[mf], &bh[j][2]);
                }
        }
    }

    // ---------------- epilogue ----------------
    const size_t coff = (size_t)blockIdx.z * sC;
#pragma unroll
    for (int mf = 0; mf < 4; mf++) {
#pragma unroll
        for (int nf = 0; nf < 8; nf++) {
            int row = blockIdx.y * 256 + wm * 64 + mf * 16 + (lane >> 2);
            int col = blockIdx.x * 128 + wn * 64 + nf * 8 + (lane & 3) * 2;
            float* a4 = acc[mf][nf];
            if (Cf) {
                *(float2*)(Cf + coff + (size_t)row * ldc + col)       = make_float2(a4[0], a4[1]);
                *(float2*)(Cf + coff + (size_t)(row + 8) * ldc + col) = make_float2(a4[2], a4[3]);
            }
            if (Ch) {
                bf16 h0 = __float2bfloat16_rn(a4[0]);
                bf16 h1 = __float2bfloat16_rn(a4[1]);
                bf16 h2 = __float2bfloat16_rn(a4[2]);
                bf16 h3 = __float2bfloat16_rn(a4[3]);
                bf16 l0 = __float2bfloat16_rn(a4[0] - __bfloat162float(h0));
                bf16 l1 = __float2bfloat16_rn(a4[1] - __bfloat162float(h1));
                bf16 l2 = __float2bfloat16_rn(a4[2] - __bfloat162float(h2));
                bf16 l3 = __float2bfloat16_rn(a4[3] - __bfloat162float(h3));
                size_t o0 = coff + (size_t)row * ldc + col;
                size_t o1 = coff + (size_t)(row + 8) * ldc + col;
                *(bf162*)(Ch + o0) = bf162(h0, h1);
                *(bf162*)(Ch + o1) = bf162(h2, h3);
                *(bf162*)(Cl + o0) = bf162(l0, l1);
                *(bf162*)(Cl + o1) = bf162(l2, l3);
            }
        }
    }
}

// ---------------- elementwise fp32 -> hi/lo bf16 split ----------------
__global__ __launch_bounds__(256)
void split_f32(const float4* __restrict__ src, bf162* __restrict__ h,
               bf162* __restrict__ l, size_t n4)
{
    size_t i = (size_t)blockIdx.x * blockDim.x + threadIdx.x;
    if (i >= n4) return;
    float4 v = src[i];
    bf16 h0 = __float2bfloat16_rn(v.x), h1 = __float2bfloat16_rn(v.y);
    bf16 h2 = __float2bfloat16_rn(v.z), h3 = __float2bfloat16_rn(v.w);
    h[2 * i]     = bf162(h0, h1);
    h[2 * i + 1] = bf162(h2, h3);
    l[2 * i]     = bf162(__float2bfloat16_rn(v.x - __bfloat162float(h0)),
                         __float2bfloat16_rn(v.y - __bfloat162float(h1)));
    l[2 * i + 1] = bf162(__float2bfloat16_rn(v.z - __bfloat162float(h2)),
                         __float2bfloat16_rn(v.w - __bfloat162float(h3)));
}

// ---------------- V transpose + split ----------------
__global__ __launch_bounds__(256)
void transpose_split(const float* __restrict__ V, bf16* __restrict__ Th,
                     bf16* __restrict__ Tl)
{
    __shared__ float t[32][33];
    int b = blockIdx.z;
    int s0 = blockIdx.x * 32, d0 = blockIdx.y * 32;
    const float* Vb = V + (size_t)b * SQ * DH;
    int x = threadIdx.x, y = threadIdx.y;
#pragma unroll
    for (int i = 0; i < 32; i += 8)
        t[y + i][x] = Vb[(size_t)(s0 + y + i) * DH + d0 + x];
    __syncthreads();
    bf16* Thb = Th + (size_t)b * DH * SQ;
    bf16* Tlb = Tl + (size_t)b * DH * SQ;
#pragma unroll
    for (int i = 0; i < 32; i += 8) {
        float v = t[x][y + i];
        bf16 hv = __float2bfloat16_rn(v);
        size_t o = (size_t)(d0 + y + i) * SQ + s0 + x;
        Thb[o] = hv;
        Tlb[o] = __float2bfloat16_rn(v - __bfloat162float(hv));
    }
}

// ---------------- masked softmax ----------------
__global__ __launch_bounds__(256)
void softmax_mask(const float* __restrict__ P, bf16* __restrict__ Ph,
                  bf16* __restrict__ Pl, const int* __restrict__ length)
{
    int row = blockIdx.x;
    int b = row >> 12;
    const float4* p4 = (const float4*)(P + (size_t)row * SQ);
    int valid = length[b] * 2;
    int t = threadIdx.x;

    float4 v[4];
    float e[16];
#pragma unroll
    for (int i = 0; i < 4; i++) v[i] = p4[i * 256 + t];

    float m = -INFINITY;
#pragma unroll
    for (int i = 0; i < 4; i++) {
        int k = (i * 256 + t) * 4;
        if (k + 0 < valid) m = fmaxf(m, v[i].x);
        if (k + 1 < valid) m = fmaxf(m, v[i].y);
        if (k + 2 < valid) m = fmaxf(m, v[i].z);
        if (k + 3 < valid) m = fmaxf(m, v[i].w);
    }
#pragma unroll
    for (int o = 16; o > 0; o >>= 1) m = fmaxf(m, __shfl_xor_sync(~0u, m, o));
    __shared__ float red[8];
    if ((t & 31) == 0) red[t >> 5] = m;
    __syncthreads();
    if (t < 8) {
        float q = red[t];
#pragma unroll
        for (int o = 4; o > 0; o >>= 1) q = fmaxf(q, __shfl_xor_sync(0xFFu, q, o));
        red[t] = q;
    }
    __syncthreads();
    float mx = red[0];
    __syncthreads();

    float s = 0.f;
#pragma unroll
    for (int i = 0; i < 4; i++) {
        int k = (i * 256 + t) * 4;
        e[4 * i + 0] = (k + 0 < valid) ? __expf(v[i].x - mx) : 0.f;
        e[4 * i + 1] = (k + 1 < valid) ? __expf(v[i].y - mx) : 0.f;
        e[4 * i + 2] = (k + 2 < valid) ? __expf(v[i].z - mx) : 0.f;
        e[4 * i + 3] = (k + 3 < valid) ? __expf(v[i].w - mx) : 0.f;
        s += e[4 * i] + e[4 * i + 1] + e[4 * i + 2] + e[4 * i + 3];
    }
#pragma unroll
    for (int o = 16; o > 0; o >>= 1) s += __shfl_xor_sync(~0u, s, o);
    __shared__ float red2[8];
    if ((t & 31) == 0) red2[t >> 5] = s;
    __syncthreads();
    if (t < 8) {
        float q = red2[t];
#pragma unroll
        for (int o = 4; o > 0; o >>= 1) q += __shfl_xor_sync(0xFFu, q, o);
        red2[t] = q;
    }
    __syncthreads();
    float inv = 1.0f / red2[0];

    bf162* ph = (bf162*)(Ph + (size_t)row * SQ);
    bf162* pl = (bf162*)(Pl + (size_t)row * SQ);
#pragma unroll
    for (int i = 0; i < 4; i++) {
#pragma unroll
        for (int j = 0; j < 2; j++) {
            float a = e[4 * i + 2 * j] * inv, c = e[4 * i + 2 * j + 1] * inv;
            bf16 ha = __float2bfloat16_rn(a), hc = __float2bfloat16_rn(c);
            bf16 la = __float2bfloat16_rn(a - __bfloat162float(ha));
            bf16 lc = __float2bfloat16_rn(c - __bfloat162float(hc));
            int o = (i * 256 + t) * 2 + j;
            ph[o] = bf162(ha, hc);
            pl[o] = bf162(la, lc);
        }
    }
}

// ---------------- host launcher ----------------
extern "C" void kernel_launch(void* const* d_in, const int* in_sizes, int n_in,
                              void* d_out, int out_size)
{
    const float* x   = (const float*)d_in[0];
    const int*   len = (const int*)d_in[1];
    const float* Wq  = (const float*)d_in[2];
    const float* Wk  = (const float*)d_in[3];
    const float* Wv  = (const float*)d_in[4];
    float* out = (float*)d_out;

    bf16 *xh, *xl, *wqh, *wql, *wkh, *wkl, *wvh, *wvl;
    bf16 *qh, *ql, *kh, *kl, *vth, *vtl, *ph, *pl;
    float *gv, *gp;
    cudaGetSymbolAddress((void**)&xh, g_Xh);   cudaGetSymbolAddress((void**)&xl, g_Xl);
    cudaGetSymbolAddress((void**)&wqh, g_Wqh); cudaGetSymbolAddress((void**)&wql, g_Wql);
    cudaGetSymbolAddress((void**)&wkh, g_Wkh); cudaGetSymbolAddress((void**)&wkl, g_Wkl);
    cudaGetSymbolAddress((void**)&wvh, g_Wvh); cudaGetSymbolAddress((void**)&wvl, g_Wvl);
    cudaGetSymbolAddress((void**)&qh, g_Qh);   cudaGetSymbolAddress((void**)&ql, g_Ql);
    cudaGetSymbolAddress((void**)&kh, g_Kh);   cudaGetSymbolAddress((void**)&kl, g_Kl);
    cudaGetSymbolAddress((void**)&gv, g_V);
    cudaGetSymbolAddress((void**)&vth, g_Vth); cudaGetSymbolAddress((void**)&vtl, g_Vtl);
    cudaGetSymbolAddress((void**)&gp, g_P);
    cudaGetSymbolAddress((void**)&ph, g_Ph);   cudaGetSymbolAddress((void**)&pl, g_Pl);

    cudaFuncSetAttribute(gemm_bf16_3p, cudaFuncAttributeMaxDynamicSharedMemorySize, SMEM_GEMM);

    // 0) split inputs/weights
    {
        size_t n4 = (size_t)MTOT * DH / 4;
        split_f32<<<(unsigned)((n4 + 255) / 256), 256>>>((const float4*)x, (bf162*)xh, (bf162*)xl, n4);
        size_t w4 = (size_t)DH * DH / 4;
        unsigned wg = (unsigned)((w4 + 255) / 256);
        split_f32<<<wg, 256>>>((const float4*)Wq, (bf162*)wqh, (bf162*)wql, w4);
        split_f32<<<wg, 256>>>((const float4*)Wk, (bf162*)wkh, (bf162*)wkl, w4);
        split_f32<<<wg, 256>>>((const float4*)Wv, (bf162*)wvh, (bf162*)wvl, w4);
    }

    // 1) projections: M=16384, N=1024, K=1024
    {
        dim3 g(DH / 128, MTOT / 256, 1), blk(256);
        gemm_bf16_3p<<<g, blk, SMEM_GEMM>>>(xh, xl, wqh, wql, nullptr, qh, ql, DH, DH, 0, 0, 0);
        gemm_bf16_3p<<<g, blk, SMEM_GEMM>>>(xh, xl, wkh, wkl, nullptr, kh, kl, DH, DH, 0, 0, 0);
        gemm_bf16_3p<<<g, blk, SMEM_GEMM>>>(xh, xl, wvh, wvl, gv, nullptr, nullptr, DH, DH, 0, 0, 0);
    }

    // 2) logits: batched M=N=4096, K=1024
    {
        dim3 g(SQ / 128, SQ / 256, BB), blk(256);
        gemm_bf16_3p<<<g, blk, SMEM_GEMM>>>(qh, ql, kh, kl, gp, nullptr, nullptr, DH, SQ,
                                            (size_t)SQ * DH, (size_t)SQ * DH, (size_t)SQ * SQ);
    }

    // 3) V -> Vt hi/lo
    {
        dim3 g(SQ / 32, DH / 32, BB);
        transpose_split<<<g, dim3(32, 8)>>>(gv, vth, vtl);
    }

    // 4) masked softmax -> P hi/lo
    softmax_mask<<<BB * SQ, 256>>>(gp, ph, pl, len);

    // 5) out = P @ V: batched M=4096, N=1024, K=4096
    {
        dim3 g(DH / 128, SQ / 256, BB), blk(256);
        gemm_bf16_3p<<<g, blk, SMEM_GEMM>>>(ph, pl, vth, vtl, out, nullptr, nullptr, SQ, DH,
                                            (size_t)SQ * SQ, (size_t)DH * SQ, (size_t)SQ * DH);
    }
}

// round 8
// speedup vs baseline: 2.4283x; 2.4283x over previous
#include <cuda_runtime.h>
#include <cuda_bf16.h>
#include <cstdint>
#include <math.h>

#define BB 4
#define SQ 4096
#define DH 1024
#define MTOT (BB * SQ)   // 16384

typedef __nv_bfloat16  bf16;
typedef __nv_bfloat162 bf162;

// ---------------- scratch planes (hi/lo bf16 split) ----------------
__device__ bf16 g_Xh[(size_t)MTOT * DH], g_Xl[(size_t)MTOT * DH];
__device__ bf16 g_Wqh[(size_t)DH * DH], g_Wql[(size_t)DH * DH];
__device__ bf16 g_Wkh[(size_t)DH * DH], g_Wkl[(size_t)DH * DH];
__device__ bf16 g_Wvh[(size_t)DH * DH], g_Wvl[(size_t)DH * DH];
__device__ bf16 g_Qh[(size_t)MTOT * DH], g_Ql[(size_t)MTOT * DH];
__device__ bf16 g_Kh[(size_t)MTOT * DH], g_Kl[(size_t)MTOT * DH];
__device__ float g_V[(size_t)MTOT * DH];
__device__ bf16 g_Vth[(size_t)MTOT * DH], g_Vtl[(size_t)MTOT * DH];
__device__ float g_P[(size_t)BB * SQ * SQ];
__device__ bf16 g_Ph[(size_t)BB * SQ * SQ], g_Pl[(size_t)BB * SQ * SQ];

// ---------------- PTX helpers ----------------
__device__ __forceinline__ uint32_t smem_u32(const void* p) {
    uint32_t a;
    asm("{ .reg .u64 t; cvta.to.shared.u64 t, %1; cvt.u32.u64 %0, t; }" : "=r"(a) : "l"(p));
    return a;
}
__device__ __forceinline__ void cp16(uint32_t dst, const void* src) {
    asm volatile("cp.async.cg.shared.global [%0], [%1], 16;" :: "r"(dst), "l"(src));
}
#define CP_COMMIT() asm volatile("cp.async.commit_group;" ::: "memory")
#define CP_WAIT1()  asm volatile("cp.async.wait_group 1;" ::: "memory")

__device__ __forceinline__ void ldm4(uint32_t* r, uint32_t a) {
    asm volatile("ldmatrix.sync.aligned.m8n8.x4.shared.b16 {%0,%1,%2,%3}, [%4];"
                 : "=r"(r[0]), "=r"(r[1]), "=r"(r[2]), "=r"(r[3]) : "r"(a));
}
__device__ __forceinline__ void ldm2(uint32_t* r, uint32_t a) {
    asm volatile("ldmatrix.sync.aligned.m8n8.x2.shared.b16 {%0,%1}, [%2];"
                 : "=r"(r[0]), "=r"(r[1]) : "r"(a));
}
__device__ __forceinline__ void mma16816(float* d, const uint32_t* a, const uint32_t* b) {
    asm volatile("mma.sync.aligned.m16n8k16.row.col.f32.bf16.bf16.f32 "
                 "{%0,%1,%2,%3}, {%4,%5,%6,%7}, {%8,%9}, {%0,%1,%2,%3};"
                 : "+f"(d[0]), "+f"(d[1]), "+f"(d[2]), "+f"(d[3])
                 : "r"(a[0]), "r"(a[1]), "r"(a[2]), "r"(a[3]), "r"(b[0]), "r"(b[1]));
}

// ---------------- GEMM config ----------------
// C[m,n] = sum_k A[m,k]*B[n,k]; bf16 hi/lo planes, K-major; 3 MMA passes.
// CTA tile 128x128x32, 256 threads (8 warps, 2x4), warp tile 64x32.
// lenmode: 0=none, 1=exit if B-tile (out cols) >= valid (logits),
//          2=clamp K-loop to valid (PV), 3=exit if A-rows%SQ >= valid (K/V proj)
#define STAGES 3
#define ROWB 80              // 32 bf16 = 64B + 16B pad
#define TILEB (128 * ROWB)   // 10240
#define STAGEB (4 * TILEB)   // 40960: [Ah | Al | Bh | Bl]
#define SMEM_GEMM (STAGES * STAGEB)

__global__ void __launch_bounds__(256, 1) gemm_bf16_3p(
    const bf16* __restrict__ Ah, const bf16* __restrict__ Al,
    const bf16* __restrict__ Bh, const bf16* __restrict__ Bl,
    float* __restrict__ Cf, bf16* __restrict__ Ch, bf16* __restrict__ Cl,
    int K, int ldc, size_t sA, size_t sB, size_t sC,
    const int* __restrict__ lenp, int lenmode)
{
    int nch = K / 32;
    if (lenmode) {
        if (lenmode == 1) {
            int valid = lenp[blockIdx.z] * 2;
            if ((int)(blockIdx.x * 128) >= valid) return;
        } else if (lenmode == 2) {
            int valid = lenp[blockIdx.z] * 2;
            int nv = (valid + 31) >> 5;
            nch = min(nch, nv);
        } else { // 3: projection of K/V — rows map to (b, s), skip s >= valid
            int b = (int)(blockIdx.y >> 5);                  // 128-row tiles, 32 per batch
            int srow = (int)(blockIdx.y * 128) & (SQ - 1);
            if (srow >= lenp[b] * 2) return;
        }
    }

    extern __shared__ char smem[];
    const uint32_t sb = smem_u32(smem);
    const int tid = threadIdx.x;
    const int wid = tid >> 5, lane = tid & 31;
    const int wm = wid & 1, wn = wid >> 1;     // 2 x 4 warps

    const size_t aoff = (size_t)blockIdx.z * sA + (size_t)(blockIdx.y * 128) * K;
    const size_t boff = (size_t)blockIdx.z * sB + (size_t)(blockIdx.x * 128) * K;
    const bf16* Abh = Ah + aoff;
    const bf16* Abl = Al + aoff;
    const bf16* Bbh = Bh + boff;
    const bf16* Bbl = Bl + boff;

    float acc[4][4][4];
#pragma unroll
    for (int i = 0; i < 4; i++)
#pragma unroll
        for (int j = 0; j < 4; j++)
#pragma unroll
            for (int q = 0; q < 4; q++) acc[i][j][q] = 0.f;

    // per-thread load indices
    const int r0 = tid >> 2;             // rows 0..63
    const int c0 = tid & 3;              // 16B chunk

    // ldmatrix coords
    const int rA = lane & 15, cA = (lane >> 4) * 8;
    const int rr = lane & 15;
    const int rB = rr & 7, cB = (rr >> 3) * 8;

#define LOAD_CHUNK(stg, ko)                                                     \
    do {                                                                        \
        uint32_t dst0 = sb + (stg) * STAGEB;                                    \
        int kk = (ko) * 32;                                                     \
        const bf16* s0 = Abh + (size_t)r0 * K + kk + c0 * 8;                    \
        const bf16* s1 = Abl + (size_t)r0 * K + kk + c0 * 8;                    \
        const bf16* s2 = Bbh + (size_t)r0 * K + kk + c0 * 8;                    \
        const bf16* s3 = Bbl + (size_t)r0 * K + kk + c0 * 8;                    \
        uint32_t d = dst0 + r0 * ROWB + c0 * 16;                                \
        cp16(d,             s0); cp16(d + TILEB,     s1);                       \
        cp16(d + 2 * TILEB, s2); cp16(d + 3 * TILEB, s3);                       \
        const size_t k64 = (size_t)64 * K;                                      \
        uint32_t d2 = d + 64 * ROWB;                                            \
        cp16(d2,             s0 + k64); cp16(d2 + TILEB,     s1 + k64);         \
        cp16(d2 + 2 * TILEB, s2 + k64); cp16(d2 + 3 * TILEB, s3 + k64);         \
    } while (0)

#pragma unroll
    for (int s = 0; s < STAGES - 1; s++) {
        if (s < nch) LOAD_CHUNK(s, s);
        CP_COMMIT();
    }

    for (int ch = 0; ch < nch; ch++) {
        CP_WAIT1();
        __syncthreads();

        // issue next stage right after the barrier (stage being filled was
        // consumed at iteration ch-1, so all warps are past it)
        int nx = ch + STAGES - 1;
        if (nx < nch) LOAD_CHUNK(nx % STAGES, nx);
        CP_COMMIT();

        const uint32_t st = sb + (ch % STAGES) * STAGEB;
        const uint32_t pAh = st + (wm * 64 + rA) * ROWB + cA * 2;
        const uint32_t pAl = pAh + TILEB;
        const uint32_t pBh = st + 2 * TILEB + (wn * 32 + rB) * ROWB + cB * 2;
        const uint32_t pBl = pBh + TILEB;

#pragma unroll
        for (int ks = 0; ks < 2; ks++) {
            const uint32_t kofs = ks * 32;   // 16 bf16 = 32B
            uint32_t ah[4][4], al[4][4], bh[4][2], bl[4][2];
#pragma unroll
            for (int mf = 0; mf < 4; mf++) {
                ldm4(ah[mf], pAh + mf * (16 * ROWB) + kofs);
                ldm4(al[mf], pAl + mf * (16 * ROWB) + kofs);
            }
#pragma unroll
            for (int nf = 0; nf < 4; nf++) {
                ldm2(bh[nf], pBh + nf * (8 * ROWB) + kofs);
                ldm2(bl[nf], pBl + nf * (8 * ROWB) + kofs);
            }
#pragma unroll
            for (int mf = 0; mf < 4; mf++)
#pragma unroll
                for (int nf = 0; nf < 4; nf++) {
                    mma16816(acc[mf][nf], ah[mf], bh[nf]);   // hi*hi
                    mma16816(acc[mf][nf], ah[mf], bl[nf]);   // hi*lo
                    mma16816(acc[mf][nf], al[mf], bh[nf]);   // lo*hi
                }
        }
    }

    // ---------------- epilogue ----------------
    const size_t coff = (size_t)blockIdx.z * sC;
#pragma unroll
    for (int mf = 0; mf < 4; mf++) {
#pragma unroll
        for (int nf = 0; nf < 4; nf++) {
            int row = blockIdx.y * 128 + wm * 64 + mf * 16 + (lane >> 2);
            int col = blockIdx.x * 128 + wn * 32 + nf * 8 + (lane & 3) * 2;
            float* a4 = acc[mf][nf];
            if (Cf) {
                *(float2*)(Cf + coff + (size_t)row * ldc + col)       = make_float2(a4[0], a4[1]);
                *(float2*)(Cf + coff + (size_t)(row + 8) * ldc + col) = make_float2(a4[2], a4[3]);
            }
            if (Ch) {
                bf16 h0 = __float2bfloat16_rn(a4[0]);
                bf16 h1 = __float2bfloat16_rn(a4[1]);
                bf16 h2 = __float2bfloat16_rn(a4[2]);
                bf16 h3 = __float2bfloat16_rn(a4[3]);
                bf16 l0 = __float2bfloat16_rn(a4[0] - __bfloat162float(h0));
                bf16 l1 = __float2bfloat16_rn(a4[1] - __bfloat162float(h1));
                bf16 l2 = __float2bfloat16_rn(a4[2] - __bfloat162float(h2));
                bf16 l3 = __float2bfloat16_rn(a4[3] - __bfloat162float(h3));
                size_t o0 = coff + (size_t)row * ldc + col;
                size_t o1 = coff + (size_t)(row + 8) * ldc + col;
                *(bf162*)(Ch + o0) = bf162(h0, h1);
                *(bf162*)(Ch + o1) = bf162(h2, h3);
                *(bf162*)(Cl + o0) = bf162(l0, l1);
                *(bf162*)(Cl + o1) = bf162(l2, l3);
            }
        }
    }
}

// ---------------- elementwise fp32 -> hi/lo bf16 split ----------------
__global__ __launch_bounds__(256)
void split_f32(const float4* __restrict__ src, bf162* __restrict__ h,
               bf162* __restrict__ l, size_t n4)
{
    size_t i = (size_t)blockIdx.x * blockDim.x + threadIdx.x;
    if (i >= n4) return;
    float4 v = src[i];
    bf16 h0 = __float2bfloat16_rn(v.x), h1 = __float2bfloat16_rn(v.y);
    bf16 h2 = __float2bfloat16_rn(v.z), h3 = __float2bfloat16_rn(v.w);
    h[2 * i]     = bf162(h0, h1);
    h[2 * i + 1] = bf162(h2, h3);
    l[2 * i]     = bf162(__float2bfloat16_rn(v.x - __bfloat162float(h0)),
                         __float2bfloat16_rn(v.y - __bfloat162float(h1)));
    l[2 * i + 1] = bf162(__float2bfloat16_rn(v.z - __bfloat162float(h2)),
                         __float2bfloat16_rn(v.w - __bfloat162float(h3)));
}

// ---------------- V transpose + split ----------------
__global__ __launch_bounds__(256)
void transpose_split(const float* __restrict__ V, bf16* __restrict__ Th,
                     bf16* __restrict__ Tl)
{
    __shared__ float t[32][33];
    int b = blockIdx.z;
    int s0 = blockIdx.x * 32, d0 = blockIdx.y * 32;
    const float* Vb = V + (size_t)b * SQ * DH;
    int x = threadIdx.x, y = threadIdx.y;
#pragma unroll
    for (int i = 0; i < 32; i += 8)
        t[y + i][x] = Vb[(size_t)(s0 + y + i) * DH + d0 + x];
    __syncthreads();
    bf16* Thb = Th + (size_t)b * DH * SQ;
    bf16* Tlb = Tl + (size_t)b * DH * SQ;
#pragma unroll
    for (int i = 0; i < 32; i += 8) {
        float v = t[x][y + i];
        bf16 hv = __float2bfloat16_rn(v);
        size_t o = (size_t)(d0 + y + i) * SQ + s0 + x;
        Thb[o] = hv;
        Tlb[o] = __float2bfloat16_rn(v - __bfloat162float(hv));
    }
}

// ---------------- masked softmax ----------------
__global__ __launch_bounds__(256)
void softmax_mask(const float* __restrict__ P, bf16* __restrict__ Ph,
                  bf16* __restrict__ Pl, const int* __restrict__ length)
{
    int row = blockIdx.x;
    int b = row >> 12;
    const float4* p4 = (const float4*)(P + (size_t)row * SQ);
    int valid = length[b] * 2;
    int t = threadIdx.x;

    float4 v[4];
    float e[16];
#pragma unroll
    for (int i = 0; i < 4; i++) v[i] = p4[i * 256 + t];

    float m = -INFINITY;
#pragma unroll
    for (int i = 0; i < 4; i++) {
        int k = (i * 256 + t) * 4;
        if (k + 0 < valid) m = fmaxf(m, v[i].x);
        if (k + 1 < valid) m = fmaxf(m, v[i].y);
        if (k + 2 < valid) m = fmaxf(m, v[i].z);
        if (k + 3 < valid) m = fmaxf(m, v[i].w);
    }
#pragma unroll
    for (int o = 16; o > 0; o >>= 1) m = fmaxf(m, __shfl_xor_sync(~0u, m, o));
    __shared__ float red[8];
    if ((t & 31) == 0) red[t >> 5] = m;
    __syncthreads();
    if (t < 8) {
        float q = red[t];
#pragma unroll
        for (int o = 4; o > 0; o >>= 1) q = fmaxf(q, __shfl_xor_sync(0xFFu, q, o));
        red[t] = q;
    }
    __syncthreads();
    float mx = red[0];
    __syncthreads();

    float s = 0.f;
#pragma unroll
    for (int i = 0; i < 4; i++) {
        int k = (i * 256 + t) * 4;
        e[4 * i + 0] = (k + 0 < valid) ? __expf(v[i].x - mx) : 0.f;
        e[4 * i + 1] = (k + 1 < valid) ? __expf(v[i].y - mx) : 0.f;
        e[4 * i + 2] = (k + 2 < valid) ? __expf(v[i].z - mx) : 0.f;
        e[4 * i + 3] = (k + 3 < valid) ? __expf(v[i].w - mx) : 0.f;
        s += e[4 * i] + e[4 * i + 1] + e[4 * i + 2] + e[4 * i + 3];
    }
#pragma unroll
    for (int o = 16; o > 0; o >>= 1) s += __shfl_xor_sync(~0u, s, o);
    __shared__ float red2[8];
    if ((t & 31) == 0) red2[t >> 5] = s;
    __syncthreads();
    if (t < 8) {
        float q = red2[t];
#pragma unroll
        for (int o = 4; o > 0; o >>= 1) q += __shfl_xor_sync(0xFFu, q, o);
        red2[t] = q;
    }
    __syncthreads();
    float inv = 1.0f / red2[0];

    bf162* ph = (bf162*)(Ph + (size_t)row * SQ);
    bf162* pl = (bf162*)(Pl + (size_t)row * SQ);
#pragma unroll
    for (int i = 0; i < 4; i++) {
#pragma unroll
        for (int j = 0; j < 2; j++) {
            float a = e[4 * i + 2 * j] * inv, c = e[4 * i + 2 * j + 1] * inv;
            bf16 ha = __float2bfloat16_rn(a), hc = __float2bfloat16_rn(c);
            bf16 la = __float2bfloat16_rn(a - __bfloat162float(ha));
            bf16 lc = __float2bfloat16_rn(c - __bfloat162float(hc));
            int o = (i * 256 + t) * 2 + j;
            ph[o] = bf162(ha, hc);
            pl[o] = bf162(la, lc);
        }
    }
}

// ---------------- host launcher ----------------
extern "C" void kernel_launch(void* const* d_in, const int* in_sizes, int n_in,
                              void* d_out, int out_size)
{
    const float* x   = (const float*)d_in[0];
    const int*   len = (const int*)d_in[1];
    const float* Wq  = (const float*)d_in[2];
    const float* Wk  = (const float*)d_in[3];
    const float* Wv  = (const float*)d_in[4];
    float* out = (float*)d_out;

    bf16 *xh, *xl, *wqh, *wql, *wkh, *wkl, *wvh, *wvl;
    bf16 *qh, *ql, *kh, *kl, *vth, *vtl, *ph, *pl;
    float *gv, *gp;
    cudaGetSymbolAddress((void**)&xh, g_Xh);   cudaGetSymbolAddress((void**)&xl, g_Xl);
    cudaGetSymbolAddress((void**)&wqh, g_Wqh); cudaGetSymbolAddress((void**)&wql, g_Wql);
    cudaGetSymbolAddress((void**)&wkh, g_Wkh); cudaGetSymbolAddress((void**)&wkl, g_Wkl);
    cudaGetSymbolAddress((void**)&wvh, g_Wvh); cudaGetSymbolAddress((void**)&wvl, g_Wvl);
    cudaGetSymbolAddress((void**)&qh, g_Qh);   cudaGetSymbolAddress((void**)&ql, g_Ql);
    cudaGetSymbolAddress((void**)&kh, g_Kh);   cudaGetSymbolAddress((void**)&kl, g_Kl);
    cudaGetSymbolAddress((void**)&gv, g_V);
    cudaGetSymbolAddress((void**)&vth, g_Vth); cudaGetSymbolAddress((void**)&vtl, g_Vtl);
    cudaGetSymbolAddress((void**)&gp, g_P);
    cudaGetSymbolAddress((void**)&ph, g_Ph);   cudaGetSymbolAddress((void**)&pl, g_Pl);

    cudaFuncSetAttribute(gemm_bf16_3p, cudaFuncAttributeMaxDynamicSharedMemorySize, SMEM_GEMM);

    // 0) split inputs/weights
    {
        size_t n4 = (size_t)MTOT * DH / 4;
        split_f32<<<(unsigned)((n4 + 255) / 256), 256>>>((const float4*)x, (bf162*)xh, (bf162*)xl, n4);
        size_t w4 = (size_t)DH * DH / 4;
        unsigned wg = (unsigned)((w4 + 255) / 256);
        split_f32<<<wg, 256>>>((const float4*)Wq, (bf162*)wqh, (bf162*)wql, w4);
        split_f32<<<wg, 256>>>((const float4*)Wk, (bf162*)wkh, (bf162*)wkl, w4);
        split_f32<<<wg, 256>>>((const float4*)Wv, (bf162*)wvh, (bf162*)wvl, w4);
    }

    // 1) projections: M=16384, N=1024, K=1024.  Q: full; K/V: skip rows >= valid.
    {
        dim3 g(DH / 128, MTOT / 128, 1), blk(256);
        gemm_bf16_3p<<<g, blk, SMEM_GEMM>>>(xh, xl, wqh, wql, nullptr, qh, ql, DH, DH, 0, 0, 0, nullptr, 0);
        gemm_bf16_3p<<<g, blk, SMEM_GEMM>>>(xh, xl, wkh, wkl, nullptr, kh, kl, DH, DH, 0, 0, 0, len, 3);
        gemm_bf16_3p<<<g, blk, SMEM_GEMM>>>(xh, xl, wvh, wvl, gv, nullptr, nullptr, DH, DH, 0, 0, 0, len, 3);
    }

    // 2) logits: batched M=N=4096, K=1024 — exit key tiles beyond valid
    {
        dim3 g(SQ / 128, SQ / 128, BB), blk(256);
        gemm_bf16_3p<<<g, blk, SMEM_GEMM>>>(qh, ql, kh, kl, gp, nullptr, nullptr, DH, SQ,
                                            (size_t)SQ * DH, (size_t)SQ * DH, (size_t)SQ * SQ, len, 1);
    }

    // 3) V -> Vt hi/lo
    {
        dim3 g(SQ / 32, DH / 32, BB);
        transpose_split<<<g, dim3(32, 8)>>>(gv, vth, vtl);
    }

    // 4) masked softmax -> P hi/lo (writes exact zeros beyond valid)
    softmax_mask<<<BB * SQ, 256>>>(gp, ph, pl, len);

    // 5) out = P @ V: batched M=4096, N=1024, K=4096 — clamp K-loop to valid
    {
        dim3 g(DH / 128, SQ / 128, BB), blk(256);
        gemm_bf16_3p<<<g, blk, SMEM_GEMM>>>(ph, pl, vth, vtl, out, nullptr, nullptr, SQ, DH,
                                            (size_t)SQ * SQ, (size_t)DH * SQ, (size_t)SQ * DH, len, 2);
    }
}

// round 10
// speedup vs baseline: 2.9801x; 1.2272x over previous
#include <cuda_runtime.h>
#include <cuda_bf16.h>
#include <cstdint>
#include <math.h>

#define BB 4
#define SQ 4096
#define DH 1024
#define MTOT (BB * SQ)   // 16384

typedef __nv_bfloat16  bf16;
typedef __nv_bfloat162 bf162;

// ---------------- scratch planes (hi/lo bf16 split) ----------------
__device__ bf16 g_Xh[(size_t)MTOT * DH], g_Xl[(size_t)MTOT * DH];
__device__ bf16 g_Wqh[(size_t)DH * DH], g_Wql[(size_t)DH * DH];
__device__ bf16 g_Wkh[(size_t)DH * DH], g_Wkl[(size_t)DH * DH];
__device__ bf16 g_Wvh[(size_t)DH * DH], g_Wvl[(size_t)DH * DH];
__device__ bf16 g_Qh[(size_t)MTOT * DH], g_Ql[(size_t)MTOT * DH];
__device__ bf16 g_Kh[(size_t)MTOT * DH], g_Kl[(size_t)MTOT * DH];
__device__ float g_V[(size_t)MTOT * DH];
__device__ bf16 g_Vth[(size_t)MTOT * DH], g_Vtl[(size_t)MTOT * DH];
__device__ float g_P[(size_t)BB * SQ * SQ];
__device__ bf16 g_Ph[(size_t)BB * SQ * SQ], g_Pl[(size_t)BB * SQ * SQ];

// ---------------- PTX helpers ----------------
__device__ __forceinline__ uint32_t smem_u32(const void* p) {
    uint32_t a;
    asm("{ .reg .u64 t; cvta.to.shared.u64 t, %1; cvt.u32.u64 %0, t; }" : "=r"(a) : "l"(p));
    return a;
}
__device__ __forceinline__ void cp16(uint32_t dst, const void* src) {
    asm volatile("cp.async.cg.shared.global [%0], [%1], 16;" :: "r"(dst), "l"(src));
}
#define CP_COMMIT() asm volatile("cp.async.commit_group;" ::: "memory")
#define CP_WAIT0()  asm volatile("cp.async.wait_group 0;" ::: "memory")

__device__ __forceinline__ void ldm4(uint32_t* r, uint32_t a) {
    asm volatile("ldmatrix.sync.aligned.m8n8.x4.shared.b16 {%0,%1,%2,%3}, [%4];"
                 : "=r"(r[0]), "=r"(r[1]), "=r"(r[2]), "=r"(r[3]) : "r"(a));
}
__device__ __forceinline__ void mma16816(float* d, const uint32_t* a, const uint32_t* b) {
    asm volatile("mma.sync.aligned.m16n8k16.row.col.f32.bf16.bf16.f32 "
                 "{%0,%1,%2,%3}, {%4,%5,%6,%7}, {%8,%9}, {%0,%1,%2,%3};"
                 : "+f"(d[0]), "+f"(d[1]), "+f"(d[2]), "+f"(d[3])
                 : "r"(a[0]), "r"(a[1]), "r"(a[2]), "r"(a[3]), "r"(b[0]), "r"(b[1]));
}

// ---------------- GEMM config ----------------
// C[m,n] = sum_k A[m,k]*B[n,k]; bf16 hi/lo planes, K-major; 3 MMA passes.
// CTA tile 128x128x32, 256 threads (8 warps, 2x4), warp tile 64x32.
// 2 stages, 2 CTAs/SM (cross-CTA latency hiding).
// lenmode: 0=none, 1=exit if out-col tile >= valid (logits),
//          2=clamp K-loop to valid (PV), 3=exit if A-rows%SQ >= valid (K/V proj)
#define STAGES 2
#define ROWB 80              // 32 bf16 = 64B + 16B pad
#define TILEB (128 * ROWB)   // 10240
#define STAGEB (4 * TILEB)   // 40960: [Ah | Al | Bh | Bl]
#define SMEM_GEMM (STAGES * STAGEB)   // 81920

__global__ void __launch_bounds__(256, 2) gemm_bf16_3p(
    const bf16* __restrict__ Ah, const bf16* __restrict__ Al,
    const bf16* __restrict__ Bh, const bf16* __restrict__ Bl,
    float* __restrict__ Cf, bf16* __restrict__ Ch, bf16* __restrict__ Cl,
    int K, int ldc, size_t sA, size_t sB, size_t sC,
    const int* __restrict__ lenp, int lenmode)
{
    int nch = K / 32;
    if (lenmode) {
        if (lenmode == 1) {
            int valid = lenp[blockIdx.z] * 2;
            if ((int)(blockIdx.x * 128) >= valid) return;
        } else if (lenmode == 2) {
            int valid = lenp[blockIdx.z] * 2;
            nch = min(nch, (valid + 31) >> 5);
        } else { // 3
            int b = (int)(blockIdx.y >> 5);
            int srow = (int)(blockIdx.y * 128) & (SQ - 1);
            if (srow >= lenp[b] * 2) return;
        }
    }

    extern __shared__ char smem[];
    const uint32_t sb = smem_u32(smem);
    const int tid = threadIdx.x;
    const int wid = tid >> 5, lane = tid & 31;
    const int wm = wid & 1, wn = wid >> 1;     // 2 x 4 warps, 64x32 warp tile

    const size_t aoff = (size_t)blockIdx.z * sA + (size_t)(blockIdx.y * 128) * K;
    const size_t boff = (size_t)blockIdx.z * sB + (size_t)(blockIdx.x * 128) * K;
    const bf16* Abh = Ah + aoff;
    const bf16* Abl = Al + aoff;
    const bf16* Bbh = Bh + boff;
    const bf16* Bbl = Bl + boff;

    float acc[4][4][4];
#pragma unroll
    for (int i = 0; i < 4; i++)
#pragma unroll
        for (int j = 0; j < 4; j++)
#pragma unroll
            for (int q = 0; q < 4; q++) acc[i][j][q] = 0.f;

    const int r0 = tid >> 2;             // rows 0..63
    const int c0 = tid & 3;              // 16B chunk

    // ldmatrix coords
    const int rA = lane & 15, cA = (lane >> 4) * 8;                 // A x4
    const int rB = (lane & 7) + ((lane >> 4) * 8);                  // B x4
    const int cBk = ((lane >> 3) & 1) * 8;

#define LOAD_CHUNK(stg, ko)                                                     \
    do {                                                                        \
        uint32_t dst0 = sb + (stg) * STAGEB;                                    \
        int kk = (ko) * 32;                                                     \
        const bf16* s0 = Abh + (size_t)r0 * K + kk + c0 * 8;                    \
        const bf16* s1 = Abl + (size_t)r0 * K + kk + c0 * 8;                    \
        const bf16* s2 = Bbh + (size_t)r0 * K + kk + c0 * 8;                    \
        const bf16* s3 = Bbl + (size_t)r0 * K + kk + c0 * 8;                    \
        uint32_t d = dst0 + r0 * ROWB + c0 * 16;                                \
        cp16(d,             s0); cp16(d + TILEB,     s1);                       \
        cp16(d + 2 * TILEB, s2); cp16(d + 3 * TILEB, s3);                       \
        const size_t k64 = (size_t)64 * K;                                      \
        uint32_t d2 = d + 64 * ROWB;                                            \
        cp16(d2,             s0 + k64); cp16(d2 + TILEB,     s1 + k64);         \
        cp16(d2 + 2 * TILEB, s2 + k64); cp16(d2 + 3 * TILEB, s3 + k64);         \
    } while (0)

    LOAD_CHUNK(0, 0);
    CP_COMMIT();

    for (int ch = 0; ch < nch; ch++) {
        CP_WAIT0();
        __syncthreads();

        int nx = ch + 1;
        if (nx < nch) {
            LOAD_CHUNK(nx & 1, nx);
        }
        CP_COMMIT();

        const uint32_t st = sb + (ch & 1) * STAGEB;
        const uint32_t pAh = st + (wm * 64 + rA) * ROWB + cA * 2;
        const uint32_t pAl = pAh + TILEB;
        const uint32_t pBh = st + 2 * TILEB + (wn * 32 + rB) * ROWB + cBk * 2;
        const uint32_t pBl = pBh + TILEB;

#pragma unroll
        for (int ks = 0; ks < 2; ks++) {
            const uint32_t kofs = ks * 32;   // 16 bf16 = 32B
            uint32_t ah[4][4], al[4][4];
#pragma unroll
            for (int mf = 0; mf < 4; mf++) {
                ldm4(ah[mf], pAh + mf * (16 * ROWB) + kofs);
                ldm4(al[mf], pAl + mf * (16 * ROWB) + kofs);
            }
#pragma unroll
            for (int jj = 0; jj < 2; jj++) {
                uint32_t bh[4], bl[4];
                ldm4(bh, pBh + jj * (16 * ROWB) + kofs);
                ldm4(bl, pBl + jj * (16 * ROWB) + kofs);
#pragma unroll
                for (int mf = 0; mf < 4; mf++) {
                    mma16816(acc[mf][2 * jj],     ah[mf], &bh[0]);   // hi*hi
                    mma16816(acc[mf][2 * jj + 1], ah[mf], &bh[2]);
                    mma16816(acc[mf][2 * jj],     ah[mf], &bl[0]);   // hi*lo
                    mma16816(acc[mf][2 * jj + 1], ah[mf], &bl[2]);
                    mma16816(acc[mf][2 * jj],     al[mf], &bh[0]);   // lo*hi
                    mma16816(acc[mf][2 * jj + 1], al[mf], &bh[2]);
                }
            }
        }
    }

    // ---------------- epilogue ----------------
    const size_t coff = (size_t)blockIdx.z * sC;
#pragma unroll
    for (int mf = 0; mf < 4; mf++) {
#pragma unroll
        for (int nf = 0; nf < 4; nf++) {
            int row = blockIdx.y * 128 + wm * 64 + mf * 16 + (lane >> 2);
            int col = blockIdx.x * 128 + wn * 32 + nf * 8 + (lane & 3) * 2;
            float* a4 = acc[mf][nf];
            if (Cf) {
                *(float2*)(Cf + coff + (size_t)row * ldc + col)       = make_float2(a4[0], a4[1]);
                *(float2*)(Cf + coff + (size_t)(row + 8) * ldc + col) = make_float2(a4[2], a4[3]);
            }
            if (Ch) {
                bf16 h0 = __float2bfloat16_rn(a4[0]);
                bf16 h1 = __float2bfloat16_rn(a4[1]);
                bf16 h2 = __float2bfloat16_rn(a4[2]);
                bf16 h3 = __float2bfloat16_rn(a4[3]);
                bf16 l0 = __float2bfloat16_rn(a4[0] - __bfloat162float(h0));
                bf16 l1 = __float2bfloat16_rn(a4[1] - __bfloat162float(h1));
                bf16 l2 = __float2bfloat16_rn(a4[2] - __bfloat162float(h2));
                bf16 l3 = __float2bfloat16_rn(a4[3] - __bfloat162float(h3));
                size_t o0 = coff + (size_t)row * ldc + col;
                size_t o1 = coff + (size_t)(row + 8) * ldc + col;
                *(bf162*)(Ch + o0) = bf162(h0, h1);
                *(bf162*)(Ch + o1) = bf162(h2, h3);
                *(bf162*)(Cl + o0) = bf162(l0, l1);
                *(bf162*)(Cl + o1) = bf162(l2, l3);
            }
        }
    }
}

// ---------------- elementwise fp32 -> hi/lo bf16 split ----------------
__global__ __launch_bounds__(256)
void split_f32(const float4* __restrict__ src, bf162* __restrict__ h,
               bf162* __restrict__ l, size_t n4)
{
    size_t i = (size_t)blockIdx.x * blockDim.x + threadIdx.x;
    if (i >= n4) return;
    float4 v = src[i];
    bf16 h0 = __float2bfloat16_rn(v.x), h1 = __float2bfloat16_rn(v.y);
    bf16 h2 = __float2bfloat16_rn(v.z), h3 = __float2bfloat16_rn(v.w);
    h[2 * i]     = bf162(h0, h1);
    h[2 * i + 1] = bf162(h2, h3);
    l[2 * i]     = bf162(__float2bfloat16_rn(v.x - __bfloat162float(h0)),
                         __float2bfloat16_rn(v.y - __bfloat162float(h1)));
    l[2 * i + 1] = bf162(__float2bfloat16_rn(v.z - __bfloat162float(h2)),
                         __float2bfloat16_rn(v.w - __bfloat162float(h3)));
}

// ---------------- V transpose + split ----------------
__global__ __launch_bounds__(256)
void transpose_split(const float* __restrict__ V, bf16* __restrict__ Th,
                     bf16* __restrict__ Tl)
{
    __shared__ float t[32][33];
    int b = blockIdx.z;
    int s0 = blockIdx.x * 32, d0 = blockIdx.y * 32;
    const float* Vb = V + (size_t)b * SQ * DH;
    int x = threadIdx.x, y = threadIdx.y;
#pragma unroll
    for (int i = 0; i < 32; i += 8)
        t[y + i][x] = Vb[(size_t)(s0 + y + i) * DH + d0 + x];
    __syncthreads();
    bf16* Thb = Th + (size_t)b * DH * SQ;
    bf16* Tlb = Tl + (size_t)b * DH * SQ;
#pragma unroll
    for (int i = 0; i < 32; i += 8) {
        float v = t[x][y + i];
        bf16 hv = __float2bfloat16_rn(v);
        size_t o = (size_t)(d0 + y + i) * SQ + s0 + x;
        Thb[o] = hv;
        Tlb[o] = __float2bfloat16_rn(v - __bfloat162float(hv));
    }
}

// ---------------- masked softmax ----------------
__global__ __launch_bounds__(256)
void softmax_mask(const float* __restrict__ P, bf16* __restrict__ Ph,
                  bf16* __restrict__ Pl, const int* __restrict__ length)
{
    int row = blockIdx.x;
    int b = row >> 12;
    const float4* p4 = (const float4*)(P + (size_t)row * SQ);
    int valid = length[b] * 2;
    int limit = (valid + 31) & ~31;   // PV reads only k < limit
    int t = threadIdx.x;

    float4 v[4];
    float e[16];
#pragma unroll
    for (int i = 0; i < 4; i++) v[i] = p4[i * 256 + t];

    float m = -INFINITY;
#pragma unroll
    for (int i = 0; i < 4; i++) {
        int k = (i * 256 + t) * 4;
        if (k + 0 < valid) m = fmaxf(m, v[i].x);
        if (k + 1 < valid) m = fmaxf(m, v[i].y);
        if (k + 2 < valid) m = fmaxf(m, v[i].z);
        if (k + 3 < valid) m = fmaxf(m, v[i].w);
    }
#pragma unroll
    for (int o = 16; o > 0; o >>= 1) m = fmaxf(m, __shfl_xor_sync(~0u, m, o));
    __shared__ float red[8];
    if ((t & 31) == 0) red[t >> 5] = m;
    __syncthreads();
    if (t < 8) {
        float q = red[t];
#pragma unroll
        for (int o = 4; o > 0; o >>= 1) q = fmaxf(q, __shfl_xor_sync(0xFFu, q, o));
        red[t] = q;
    }
    __syncthreads();
    float mx = red[0];
    __syncthreads();

    float s = 0.f;
#pragma unroll
    for (int i = 0; i < 4; i++) {
        int k = (i * 256 + t) * 4;
        e[4 * i + 0] = (k + 0 < valid) ? __expf(v[i].x - mx) : 0.f;
        e[4 * i + 1] = (k + 1 < valid) ? __expf(v[i].y - mx) : 0.f;
        e[4 * i + 2] = (k + 2 < valid) ? __expf(v[i].z - mx) : 0.f;
        e[4 * i + 3] = (k + 3 < valid) ? __expf(v[i].w - mx) : 0.f;
        s += e[4 * i] + e[4 * i + 1] + e[4 * i + 2] + e[4 * i + 3];
    }
#pragma unroll
    for (int o = 16; o > 0; o >>= 1) s += __shfl_xor_sync(~0u, s, o);
    __shared__ float red2[8];
    if ((t & 31) == 0) red2[t >> 5] = s;
    __syncthreads();
    if (t < 8) {
        float q = red2[t];
#pragma unroll
        for (int o = 4; o > 0; o >>= 1) q += __shfl_xor_sync(0xFFu, q, o);
        red2[t] = q;
    }
    __syncthreads();
    float inv = 1.0f / red2[0];

    bf162* ph = (bf162*)(Ph + (size_t)row * SQ);
    bf162* pl = (bf162*)(Pl + (size_t)row * SQ);
#pragma unroll
    for (int i = 0; i < 4; i++) {
#pragma unroll
        for (int j = 0; j < 2; j++) {
            int k = (i * 256 + t) * 4 + 2 * j;
            if (k >= limit) continue;
            float a = e[4 * i + 2 * j] * inv, c = e[4 * i + 2 * j + 1] * inv;
            bf16 ha = __float2bfloat16_rn(a), hc = __float2bfloat16_rn(c);
            bf16 la = __float2bfloat16_rn(a - __bfloat162float(ha));
            bf16 lc = __float2bfloat16_rn(c - __bfloat162float(hc));
            int o = (i * 256 + t) * 2 + j;
            ph[o] = bf162(ha, hc);
            pl[o] = bf162(la, lc);
        }
    }
}

// ---------------- host launcher ----------------
extern "C" void kernel_launch(void* const* d_in, const int* in_sizes, int n_in,
                              void* d_out, int out_size)
{
    const float* x   = (const float*)d_in[0];
    const int*   len = (const int*)d_in[1];
    const float* Wq  = (const float*)d_in[2];
    const float* Wk  = (const float*)d_in[3];
    const float* Wv  = (const float*)d_in[4];
    float* out = (float*)d_out;

    bf16 *xh, *xl, *wqh, *wql, *wkh, *wkl, *wvh, *wvl;
    bf16 *qh, *ql, *kh, *kl, *vth, *vtl, *ph, *pl;
    float *gv, *gp;
    cudaGetSymbolAddress((void**)&xh, g_Xh);   cudaGetSymbolAddress((void**)&xl, g_Xl);
    cudaGetSymbolAddress((void**)&wqh, g_Wqh); cudaGetSymbolAddress((void**)&wql, g_Wql);
    cudaGetSymbolAddress((void**)&wkh, g_Wkh); cudaGetSymbolAddress((void**)&wkl, g_Wkl);
    cudaGetSymbolAddress((void**)&wvh, g_Wvh); cudaGetSymbolAddress((void**)&wvl, g_Wvl);
    cudaGetSymbolAddress((void**)&qh, g_Qh);   cudaGetSymbolAddress((void**)&ql, g_Ql);
    cudaGetSymbolAddress((void**)&kh, g_Kh);   cudaGetSymbolAddress((void**)&kl, g_Kl);
    cudaGetSymbolAddress((void**)&gv, g_V);
    cudaGetSymbolAddress((void**)&vth, g_Vth); cudaGetSymbolAddress((void**)&vtl, g_Vtl);
    cudaGetSymbolAddress((void**)&gp, g_P);
    cudaGetSymbolAddress((void**)&ph, g_Ph);   cudaGetSymbolAddress((void**)&pl, g_Pl);

    cudaFuncSetAttribute(gemm_bf16_3p, cudaFuncAttributeMaxDynamicSharedMemorySize, SMEM_GEMM);

    // 0) split inputs/weights
    {
        size_t n4 = (size_t)MTOT * DH / 4;
        split_f32<<<(unsigned)((n4 + 255) / 256), 256>>>((const float4*)x, (bf162*)xh, (bf162*)xl, n4);
        size_t w4 = (size_t)DH * DH / 4;
        unsigned wg = (unsigned)((w4 + 255) / 256);
        split_f32<<<wg, 256>>>((const float4*)Wq, (bf162*)wqh, (bf162*)wql, w4);
        split_f32<<<wg, 256>>>((const float4*)Wk, (bf162*)wkh, (bf162*)wkl, w4);
        split_f32<<<wg, 256>>>((const float4*)Wv, (bf162*)wvh, (bf162*)wvl, w4);
    }

    // 1) projections: M=16384, N=1024, K=1024.  Q: full; K/V: skip rows >= valid.
    {
        dim3 g(DH / 128, MTOT / 128, 1), blk(256);
        gemm_bf16_3p<<<g, blk, SMEM_GEMM>>>(xh, xl, wqh, wql, nullptr, qh, ql, DH, DH, 0, 0, 0, nullptr, 0);
        gemm_bf16_3p<<<g, blk, SMEM_GEMM>>>(xh, xl, wkh, wkl, nullptr, kh, kl, DH, DH, 0, 0, 0, len, 3);
        gemm_bf16_3p<<<g, blk, SMEM_GEMM>>>(xh, xl, wvh, wvl, gv, nullptr, nullptr, DH, DH, 0, 0, 0, len, 3);
    }

    // 2) logits: batched M=N=4096, K=1024 — exit key tiles beyond valid
    {
        dim3 g(SQ / 128, SQ / 128, BB), blk(256);
        gemm_bf16_3p<<<g, blk, SMEM_GEMM>>>(qh, ql, kh, kl, gp, nullptr, nullptr, DH, SQ,
                                            (size_t)SQ * DH, (size_t)SQ * DH, (size_t)SQ * SQ, len, 1);
    }

    // 3) V -> Vt hi/lo
    {
        dim3 g(SQ / 32, DH / 32, BB);
        transpose_split<<<g, dim3(32, 8)>>>(gv, vth, vtl);
    }

    // 4) masked softmax -> P hi/lo (zeros up to round32(valid))
    softmax_mask<<<BB * SQ, 256>>>(gp, ph, pl, len);

    // 5) out = P @ V: batched M=4096, N=1024, K=4096 — clamp K-loop to valid
    {
        dim3 g(DH / 128, SQ / 128, BB), blk(256);
        gemm_bf16_3p<<<g, blk, SMEM_GEMM>>>(ph, pl, vth, vtl, out, nullptr, nullptr, SQ, DH,
                                            (size_t)SQ * SQ, (size_t)DH * SQ, (size_t)SQ * DH, len, 2);
    }
}

// round 12
// speedup vs baseline: 3.0660x; 1.0288x over previous
#include <cuda_runtime.h>
#include <cuda_bf16.h>
#include <cstdint>
#include <math.h>

#define BB 4
#define SQ 4096
#define DH 1024
#define MTOT (BB * SQ)   // 16384

typedef __nv_bfloat16  bf16;
typedef __nv_bfloat162 bf162;

// ---------------- scratch planes (hi/lo bf16 split) ----------------
__device__ bf16 g_Xh[(size_t)MTOT * DH], g_Xl[(size_t)MTOT * DH];
__device__ bf16 g_Wqh[(size_t)DH * DH], g_Wql[(size_t)DH * DH];
__device__ bf16 g_Wkh[(size_t)DH * DH], g_Wkl[(size_t)DH * DH];
__device__ bf16 g_Wvh[(size_t)DH * DH], g_Wvl[(size_t)DH * DH];
__device__ bf16 g_Qh[(size_t)MTOT * DH], g_Ql[(size_t)MTOT * DH];
__device__ bf16 g_Kh[(size_t)MTOT * DH], g_Kl[(size_t)MTOT * DH];
__device__ float g_V[(size_t)MTOT * DH];
__device__ bf16 g_Vth[(size_t)MTOT * DH], g_Vtl[(size_t)MTOT * DH];
__device__ float g_P[(size_t)BB * SQ * SQ];
__device__ bf16 g_Ph[(size_t)BB * SQ * SQ], g_Pl[(size_t)BB * SQ * SQ];

// ---------------- PTX helpers ----------------
__device__ __forceinline__ uint32_t smem_u32(const void* p) {
    uint32_t a;
    asm("{ .reg .u64 t; cvta.to.shared.u64 t, %1; cvt.u32.u64 %0, t; }" : "=r"(a) : "l"(p));
    return a;
}
__device__ __forceinline__ void cp16(uint32_t dst, const void* src) {
    asm volatile("cp.async.cg.shared.global [%0], [%1], 16;" :: "r"(dst), "l"(src));
}
#define CP_COMMIT() asm volatile("cp.async.commit_group;" ::: "memory")
#define CP_WAIT0()  asm volatile("cp.async.wait_group 0;" ::: "memory")

__device__ __forceinline__ void ldm4(uint32_t* r, uint32_t a) {
    asm volatile("ldmatrix.sync.aligned.m8n8.x4.shared.b16 {%0,%1,%2,%3}, [%4];"
                 : "=r"(r[0]), "=r"(r[1]), "=r"(r[2]), "=r"(r[3]) : "r"(a));
}
__device__ __forceinline__ void mma16816(float* d, const uint32_t* a, const uint32_t* b) {
    asm volatile("mma.sync.aligned.m16n8k16.row.col.f32.bf16.bf16.f32 "
                 "{%0,%1,%2,%3}, {%4,%5,%6,%7}, {%8,%9}, {%0,%1,%2,%3};"
                 : "+f"(d[0]), "+f"(d[1]), "+f"(d[2]), "+f"(d[3])
                 : "r"(a[0]), "r"(a[1]), "r"(a[2]), "r"(a[3]), "r"(b[0]), "r"(b[1]));
}

// ---------------- GEMM config ----------------
// C[m,n] = sum_k A[m,k]*B[n,k]; bf16 hi/lo planes, K-major; 3 MMA passes.
// CTA tile 128x128x32; 128 threads (4 warps, 2x2); warp tile 64x64.
// 2 stages, 2 CTAs/SM.
// lenmode: 0=none, 1=exit if out-col tile >= valid (logits),
//          2=clamp K-loop to valid (PV), 3=exit if A-rows%SQ >= valid (K/V proj)
#define NTH 128
#define STAGES 2
#define ROWB 80              // 32 bf16 = 64B + 16B pad
#define TILEB (128 * ROWB)   // 10240
#define STAGEB (4 * TILEB)   // 40960: [Ah | Al | Bh | Bl]
#define SMEM_GEMM (STAGES * STAGEB)   // 81920

__global__ void __launch_bounds__(NTH, 2) gemm_bf16_3p(
    const bf16* __restrict__ Ah, const bf16* __restrict__ Al,
    const bf16* __restrict__ Bh, const bf16* __restrict__ Bl,
    float* __restrict__ Cf, bf16* __restrict__ Ch, bf16* __restrict__ Cl,
    int K, int ldc, size_t sA, size_t sB, size_t sC,
    const int* __restrict__ lenp, int lenmode)
{
    int nch = K / 32;
    if (lenmode) {
        if (lenmode == 1) {
            int valid = lenp[blockIdx.z] * 2;
            if ((int)(blockIdx.x * 128) >= valid) return;
        } else if (lenmode == 2) {
            int valid = lenp[blockIdx.z] * 2;
            nch = min(nch, (valid + 31) >> 5);
        } else { // 3
            int b = (int)(blockIdx.y >> 5);
            int srow = (int)(blockIdx.y * 128) & (SQ - 1);
            if (srow >= lenp[b] * 2) return;
        }
    }

    extern __shared__ char smem[];
    const uint32_t sb = smem_u32(smem);
    const int tid = threadIdx.x;
    const int wid = tid >> 5, lane = tid & 31;
    const int wm = wid & 1, wn = wid >> 1;     // 2 x 2 warps, 64x64 warp tile

    const size_t aoff = (size_t)blockIdx.z * sA + (size_t)(blockIdx.y * 128) * K;
    const size_t boff = (size_t)blockIdx.z * sB + (size_t)(blockIdx.x * 128) * K;
    const bf16* Abh = Ah + aoff;
    const bf16* Abl = Al + aoff;
    const bf16* Bbh = Bh + boff;
    const bf16* Bbl = Bl + boff;

    float acc[4][8][4];
#pragma unroll
    for (int i = 0; i < 4; i++)
#pragma unroll
        for (int j = 0; j < 8; j++)
#pragma unroll
            for (int q = 0; q < 4; q++) acc[i][j][q] = 0.f;

    // cp.async: per plane, thread covers rows r0+{0,32,64,96}, 16B chunk c0
    const int r0 = tid >> 2;             // 0..31
    const int c0 = tid & 3;              // 16B chunk 0..3

    // ldmatrix coords
    const int rA = lane & 15, cA = (lane >> 4) * 8;                 // A x4
    const int rB = (lane & 7) + ((lane >> 4) * 8);                  // B x4 (2 n-frags)
    const int cBk = ((lane >> 3) & 1) * 8;

#define LOAD_CHUNK(stg, ko)                                                     \
    do {                                                                        \
        uint32_t dst0 = sb + (stg) * STAGEB;                                    \
        int kk = (ko) * 32;                                                     \
        _Pragma("unroll")                                                       \
        for (int i = 0; i < 4; i++) {                                           \
            int r = r0 + i * 32;                                                \
            uint32_t d = dst0 + r * ROWB + c0 * 16;                             \
            const size_t go = (size_t)r * K + kk + c0 * 8;                      \
            cp16(d,             Abh + go);                                      \
            cp16(d + TILEB,     Abl + go);                                      \
            cp16(d + 2 * TILEB, Bbh + go);                                      \
            cp16(d + 3 * TILEB, Bbl + go);                                      \
        }                                                                       \
    } while (0)

    LOAD_CHUNK(0, 0);
    CP_COMMIT();

    for (int ch = 0; ch < nch; ch++) {
        CP_WAIT0();
        __syncthreads();

        int nx = ch + 1;
        if (nx < nch) {
            LOAD_CHUNK(nx & 1, nx);
        }
        CP_COMMIT();

        const uint32_t st = sb + (ch & 1) * STAGEB;
        const uint32_t pAh = st + (wm * 64 + rA) * ROWB + cA * 2;
        const uint32_t pAl = pAh + TILEB;
        const uint32_t pBh = st + 2 * TILEB + (wn * 64 + rB) * ROWB + cBk * 2;
        const uint32_t pBl = pBh + TILEB;

#pragma unroll
        for (int ks = 0; ks < 2; ks++) {
            const uint32_t kofs = ks * 32;   // 16 bf16 = 32B
            uint32_t ah[4][4], al[4][4];
#pragma unroll
            for (int mf = 0; mf < 4; mf++) {
                ldm4(ah[mf], pAh + mf * (16 * ROWB) + kofs);
                ldm4(al[mf], pAl + mf * (16 * ROWB) + kofs);
            }
#pragma unroll
            for (int jj = 0; jj < 4; jj++) {
                uint32_t bh[4], bl[4];
                ldm4(bh, pBh + jj * (16 * ROWB) + kofs);
                ldm4(bl, pBl + jj * (16 * ROWB) + kofs);
#pragma unroll
                for (int mf = 0; mf < 4; mf++) {
                    mma16816(acc[mf][2 * jj],     ah[mf], &bh[0]);   // hi*hi
                    mma16816(acc[mf][2 * jj + 1], ah[mf], &bh[2]);
                    mma16816(acc[mf][2 * jj],     ah[mf], &bl[0]);   // hi*lo
                    mma16816(acc[mf][2 * jj + 1], ah[mf], &bl[2]);
                    mma16816(acc[mf][2 * jj],     al[mf], &bh[0]);   // lo*hi
                    mma16816(acc[mf][2 * jj + 1], al[mf], &bh[2]);
                }
            }
        }
    }

    // ---------------- epilogue ----------------
    const size_t coff = (size_t)blockIdx.z * sC;
#pragma unroll
    for (int mf = 0; mf < 4; mf++) {
#pragma unroll
        for (int nf = 0; nf < 8; nf++) {
            int row = blockIdx.y * 128 + wm * 64 + mf * 16 + (lane >> 2);
            int col = blockIdx.x * 128 + wn * 64 + nf * 8 + (lane & 3) * 2;
            float* a4 = acc[mf][nf];
            if (Cf) {
                *(float2*)(Cf + coff + (size_t)row * ldc + col)       = make_float2(a4[0], a4[1]);
                *(float2*)(Cf + coff + (size_t)(row + 8) * ldc + col) = make_float2(a4[2], a4[3]);
            }
            if (Ch) {
                bf16 h0 = __float2bfloat16_rn(a4[0]);
                bf16 h1 = __float2bfloat16_rn(a4[1]);
                bf16 h2 = __float2bfloat16_rn(a4[2]);
                bf16 h3 = __float2bfloat16_rn(a4[3]);
                bf16 l0 = __float2bfloat16_rn(a4[0] - __bfloat162float(h0));
                bf16 l1 = __float2bfloat16_rn(a4[1] - __bfloat162float(h1));
                bf16 l2 = __float2bfloat16_rn(a4[2] - __bfloat162float(h2));
                bf16 l3 = __float2bfloat16_rn(a4[3] - __bfloat162float(h3));
                size_t o0 = coff + (size_t)row * ldc + col;
                size_t o1 = coff + (size_t)(row + 8) * ldc + col;
                *(bf162*)(Ch + o0) = bf162(h0, h1);
                *(bf162*)(Ch + o1) = bf162(h2, h3);
                *(bf162*)(Cl + o0) = bf162(l0, l1);
                *(bf162*)(Cl + o1) = bf162(l2, l3);
            }
        }
    }
}

// ---------------- elementwise fp32 -> hi/lo bf16 split ----------------
__global__ __launch_bounds__(256)
void split_f32(const float4* __restrict__ src, bf162* __restrict__ h,
               bf162* __restrict__ l, size_t n4)
{
    size_t i = (size_t)blockIdx.x * blockDim.x + threadIdx.x;
    if (i >= n4) return;
    float4 v = src[i];
    bf16 h0 = __float2bfloat16_rn(v.x), h1 = __float2bfloat16_rn(v.y);
    bf16 h2 = __float2bfloat16_rn(v.z), h3 = __float2bfloat16_rn(v.w);
    h[2 * i]     = bf162(h0, h1);
    h[2 * i + 1] = bf162(h2, h3);
    l[2 * i]     = bf162(__float2bfloat16_rn(v.x - __bfloat162float(h0)),
                         __float2bfloat16_rn(v.y - __bfloat162float(h1)));
    l[2 * i + 1] = bf162(__float2bfloat16_rn(v.z - __bfloat162float(h2)),
                         __float2bfloat16_rn(v.w - __bfloat162float(h3)));
}

// ---------------- V transpose + split ----------------
__global__ __launch_bounds__(256)
void transpose_split(const float* __restrict__ V, bf16* __restrict__ Th,
                     bf16* __restrict__ Tl)
{
    __shared__ float t[32][33];
    int b = blockIdx.z;
    int s0 = blockIdx.x * 32, d0 = blockIdx.y * 32;
    const float* Vb = V + (size_t)b * SQ * DH;
    int x = threadIdx.x, y = threadIdx.y;
#pragma unroll
    for (int i = 0; i < 32; i += 8)
        t[y + i][x] = Vb[(size_t)(s0 + y + i) * DH + d0 + x];
    __syncthreads();
    bf16* Thb = Th + (size_t)b * DH * SQ;
    bf16* Tlb = Tl + (size_t)b * DH * SQ;
#pragma unroll
    for (int i = 0; i < 32; i += 8) {
        float v = t[x][y + i];
        bf16 hv = __float2bfloat16_rn(v);
        size_t o = (size_t)(d0 + y + i) * SQ + s0 + x;
        Thb[o] = hv;
        Tlb[o] = __float2bfloat16_rn(v - __bfloat162float(hv));
    }
}

// ---------------- masked softmax ----------------
__global__ __launch_bounds__(256)
void softmax_mask(const float* __restrict__ P, bf16* __restrict__ Ph,
                  bf16* __restrict__ Pl, const int* __restrict__ length)
{
    int row = blockIdx.x;
    int b = row >> 12;
    const float4* p4 = (const float4*)(P + (size_t)row * SQ);
    int valid = length[b] * 2;
    int limit = (valid + 31) & ~31;   // PV reads only k < limit
    int t = threadIdx.x;

    float4 v[4];
    float e[16];
#pragma unroll
    for (int i = 0; i < 4; i++) v[i] = p4[i * 256 + t];

    float m = -INFINITY;
#pragma unroll
    for (int i = 0; i < 4; i++) {
        int k = (i * 256 + t) * 4;
        if (k + 0 < valid) m = fmaxf(m, v[i].x);
        if (k + 1 < valid) m = fmaxf(m, v[i].y);
        if (k + 2 < valid) m = fmaxf(m, v[i].z);
        if (k + 3 < valid) m = fmaxf(m, v[i].w);
    }
#pragma unroll
    for (int o = 16; o > 0; o >>= 1) m = fmaxf(m, __shfl_xor_sync(~0u, m, o));
    __shared__ float red[8];
    if ((t & 31) == 0) red[t >> 5] = m;
    __syncthreads();
    if (t < 8) {
        float q = red[t];
#pragma unroll
        for (int o = 4; o > 0; o >>= 1) q = fmaxf(q, __shfl_xor_sync(0xFFu, q, o));
        red[t] = q;
    }
    __syncthreads();
    float mx = red[0];
    __syncthreads();

    float s = 0.f;
#pragma unroll
    for (int i = 0; i < 4; i++) {
        int k = (i * 256 + t) * 4;
        e[4 * i + 0] = (k + 0 < valid) ? __expf(v[i].x - mx) : 0.f;
        e[4 * i + 1] = (k + 1 < valid) ? __expf(v[i].y - mx) : 0.f;
        e[4 * i + 2] = (k + 2 < valid) ? __expf(v[i].z - mx) : 0.f;
        e[4 * i + 3] = (k + 3 < valid) ? __expf(v[i].w - mx) : 0.f;
        s += e[4 * i] + e[4 * i + 1] + e[4 * i + 2] + e[4 * i + 3];
    }
#pragma unroll
    for (int o = 16; o > 0; o >>= 1) s += __shfl_xor_sync(~0u, s, o);
    __shared__ float red2[8];
    if ((t & 31) == 0) red2[t >> 5] = s;
    __syncthreads();
    if (t < 8) {
        float q = red2[t];
#pragma unroll
        for (int o = 4; o > 0; o >>= 1) q += __shfl_xor_sync(0xFFu, q, o);
        red2[t] = q;
    }
    __syncthreads();
    float inv = 1.0f / red2[0];

    bf162* ph = (bf162*)(Ph + (size_t)row * SQ);
    bf162* pl = (bf162*)(Pl + (size_t)row * SQ);
#pragma unroll
    for (int i = 0; i < 4; i++) {
#pragma unroll
        for (int j = 0; j < 2; j++) {
            int k = (i * 256 + t) * 4 + 2 * j;
            if (k >= limit) continue;
            float a = e[4 * i + 2 * j] * inv, c = e[4 * i + 2 * j + 1] * inv;
            bf16 ha = __float2bfloat16_rn(a), hc = __float2bfloat16_rn(c);
            bf16 la = __float2bfloat16_rn(a - __bfloat162float(ha));
            bf16 lc = __float2bfloat16_rn(c - __bfloat162float(hc));
            int o = (i * 256 + t) * 2 + j;
            ph[o] = bf162(ha, hc);
            pl[o] = bf162(la, lc);
        }
    }
}

// ---------------- host launcher ----------------
extern "C" void kernel_launch(void* const* d_in, const int* in_sizes, int n_in,
                              void* d_out, int out_size)
{
    const float* x   = (const float*)d_in[0];
    const int*   len = (const int*)d_in[1];
    const float* Wq  = (const float*)d_in[2];
    const float* Wk  = (const float*)d_in[3];
    const float* Wv  = (const float*)d_in[4];
    float* out = (float*)d_out;

    bf16 *xh, *xl, *wqh, *wql, *wkh, *wkl, *wvh, *wvl;
    bf16 *qh, *ql, *kh, *kl, *vth, *vtl, *ph, *pl;
    float *gv, *gp;
    cudaGetSymbolAddress((void**)&xh, g_Xh);   cudaGetSymbolAddress((void**)&xl, g_Xl);
    cudaGetSymbolAddress((void**)&wqh, g_Wqh); cudaGetSymbolAddress((void**)&wql, g_Wql);
    cudaGetSymbolAddress((void**)&wkh, g_Wkh); cudaGetSymbolAddress((void**)&wkl, g_Wkl);
    cudaGetSymbolAddress((void**)&wvh, g_Wvh); cudaGetSymbolAddress((void**)&wvl, g_Wvl);
    cudaGetSymbolAddress((void**)&qh, g_Qh);   cudaGetSymbolAddress((void**)&ql, g_Ql);
    cudaGetSymbolAddress((void**)&kh, g_Kh);   cudaGetSymbolAddress((void**)&kl, g_Kl);
    cudaGetSymbolAddress((void**)&gv, g_V);
    cudaGetSymbolAddress((void**)&vth, g_Vth); cudaGetSymbolAddress((void**)&vtl, g_Vtl);
    cudaGetSymbolAddress((void**)&gp, g_P);
    cudaGetSymbolAddress((void**)&ph, g_Ph);   cudaGetSymbolAddress((void**)&pl, g_Pl);

    cudaFuncSetAttribute(gemm_bf16_3p, cudaFuncAttributeMaxDynamicSharedMemorySize, SMEM_GEMM);

    // 0) split inputs/weights
    {
        size_t n4 = (size_t)MTOT * DH / 4;
        split_f32<<<(unsigned)((n4 + 255) / 256), 256>>>((const float4*)x, (bf162*)xh, (bf162*)xl, n4);
        size_t w4 = (size_t)DH * DH / 4;
        unsigned wg = (unsigned)((w4 + 255) / 256);
        split_f32<<<wg, 256>>>((const float4*)Wq, (bf162*)wqh, (bf162*)wql, w4);
        split_f32<<<wg, 256>>>((const float4*)Wk, (bf162*)wkh, (bf162*)wkl, w4);
        split_f32<<<wg, 256>>>((const float4*)Wv, (bf162*)wvh, (bf162*)wvl, w4);
    }

    dim3 blk(NTH);

    // 1) projections: M=16384, N=1024, K=1024.  Q: full; K/V: skip rows >= valid.
    {
        dim3 g(DH / 128, MTOT / 128, 1);
        gemm_bf16_3p<<<g, blk, SMEM_GEMM>>>(xh, xl, wqh, wql, nullptr, qh, ql, DH, DH, 0, 0, 0, nullptr, 0);
        gemm_bf16_3p<<<g, blk, SMEM_GEMM>>>(xh, xl, wkh, wkl, nullptr, kh, kl, DH, DH, 0, 0, 0, len, 3);
        gemm_bf16_3p<<<g, blk, SMEM_GEMM>>>(xh, xl, wvh, wvl, gv, nullptr, nullptr, DH, DH, 0, 0, 0, len, 3);
    }

    // 2) logits: batched M=N=4096, K=1024 — exit key tiles beyond valid
    {
        dim3 g(SQ / 128, SQ / 128, BB);
        gemm_bf16_3p<<<g, blk, SMEM_GEMM>>>(qh, ql, kh, kl, gp, nullptr, nullptr, DH, SQ,
                                            (size_t)SQ * DH, (size_t)SQ * DH, (size_t)SQ * SQ, len, 1);
    }

    // 3) V -> Vt hi/lo
    {
        dim3 g(SQ / 32, DH / 32, BB);
        transpose_split<<<g, dim3(32, 8)>>>(gv, vth, vtl);
    }

    // 4) masked softmax -> P hi/lo (zeros up to round32(valid))
    softmax_mask<<<BB * SQ, 256>>>(gp, ph, pl, len);

    // 5) out = P @ V: batched M=4096, N=1024, K=4096 — clamp K-loop to valid
    {
        dim3 g(DH / 128, SQ / 128, BB);
        gemm_bf16_3p<<<g, blk, SMEM_GEMM>>>(ph, pl, vth, vtl, out, nullptr, nullptr, SQ, DH,
                                            (size_t)SQ * SQ, (size_t)DH * SQ, (size_t)SQ * DH, len, 2);
    }
}

// round 13
// speedup vs baseline: 3.2833x; 1.0709x over previous
#include <cuda_runtime.h>
#include <cuda_bf16.h>
#include <cstdint>
#include <math.h>

#define BB 4
#define SQ 4096
#define DH 1024
#define MTOT (BB * SQ)   // 16384

typedef __nv_bfloat16  bf16;
typedef __nv_bfloat162 bf162;

// ---------------- scratch planes (hi/lo bf16 split) ----------------
__device__ bf16 g_Xh[(size_t)MTOT * DH], g_Xl[(size_t)MTOT * DH];
__device__ bf16 g_Wqh[(size_t)DH * DH], g_Wql[(size_t)DH * DH];
__device__ bf16 g_Wkh[(size_t)DH * DH], g_Wkl[(size_t)DH * DH];
__device__ bf16 g_Wvh[(size_t)DH * DH], g_Wvl[(size_t)DH * DH];
__device__ bf16 g_Qh[(size_t)MTOT * DH], g_Ql[(size_t)MTOT * DH];
__device__ bf16 g_Kh[(size_t)MTOT * DH], g_Kl[(size_t)MTOT * DH];
__device__ float g_V[(size_t)MTOT * DH];
__device__ bf16 g_Vth[(size_t)MTOT * DH], g_Vtl[(size_t)MTOT * DH];
__device__ float g_P[(size_t)BB * SQ * SQ];
__device__ bf16 g_Ph[(size_t)BB * SQ * SQ], g_Pl[(size_t)BB * SQ * SQ];

// ---------------- PTX helpers ----------------
__device__ __forceinline__ uint32_t smem_u32(const void* p) {
    uint32_t a;
    asm("{ .reg .u64 t; cvta.to.shared.u64 t, %1; cvt.u32.u64 %0, t; }" : "=r"(a) : "l"(p));
    return a;
}
__device__ __forceinline__ void cp16(uint32_t dst, const void* src) {
    asm volatile("cp.async.cg.shared.global [%0], [%1], 16;" :: "r"(dst), "l"(src));
}
#define CP_COMMIT() asm volatile("cp.async.commit_group;" ::: "memory")
#define CP_WAIT1()  asm volatile("cp.async.wait_group 1;" ::: "memory")

__device__ __forceinline__ void ldm4(uint32_t* r, uint32_t a) {
    asm volatile("ldmatrix.sync.aligned.m8n8.x4.shared.b16 {%0,%1,%2,%3}, [%4];"
                 : "=r"(r[0]), "=r"(r[1]), "=r"(r[2]), "=r"(r[3]) : "r"(a));
}
__device__ __forceinline__ void mma16816(float* d, const uint32_t* a, const uint32_t* b) {
    asm volatile("mma.sync.aligned.m16n8k16.row.col.f32.bf16.bf16.f32 "
                 "{%0,%1,%2,%3}, {%4,%5,%6,%7}, {%8,%9}, {%0,%1,%2,%3};"
                 : "+f"(d[0]), "+f"(d[1]), "+f"(d[2]), "+f"(d[3])
                 : "r"(a[0]), "r"(a[1]), "r"(a[2]), "r"(a[3]), "r"(b[0]), "r"(b[1]));
}

// 64B-row swizzle: 16B-lane c (0..3) XORed with (row>>1)&3 — conflict-free
// for ldmatrix (8 consecutive rows cover all 8 16B banks-groups) and STS.
__device__ __forceinline__ uint32_t sw64(int row, int c16) {
    return (uint32_t)(row * 64 + ((c16 ^ ((row >> 1) & 3)) << 4));
}

// ---------------- GEMM config ----------------
// C[m,n] = sum_k A[m,k]*B[n,k]; bf16 hi/lo planes, K-major; 3 MMA passes.
// CTA tile 128x128x32; 128 threads (4 warps, 2x2); warp tile 64x64.
// 3 stages (swizzled, 32KB each), loads 2 chunks ahead, 2 CTAs/SM.
#define NTH 128
#define STAGES 3
#define TILEB (128 * 64)     // 8192: one plane
#define STAGEB (4 * TILEB)   // 32768: [Ah | Al | Bh | Bl]
#define SMEM_GEMM (STAGES * STAGEB)   // 98304

__global__ void __launch_bounds__(NTH, 2) gemm_bf16_3p(
    const bf16* __restrict__ Ah, const bf16* __restrict__ Al,
    const bf16* __restrict__ Bh, const bf16* __restrict__ Bl,
    float* __restrict__ Cf, bf16* __restrict__ Ch, bf16* __restrict__ Cl,
    int K, int ldc, size_t sA, size_t sB, size_t sC,
    const int* __restrict__ lenp, int lenmode)
{
    int nch = K / 32;
    if (lenmode) {
        if (lenmode == 1) {
            int valid = lenp[blockIdx.z] * 2;
            if ((int)(blockIdx.x * 128) >= valid) return;
        } else if (lenmode == 2) {
            int valid = lenp[blockIdx.z] * 2;
            nch = min(nch, (valid + 31) >> 5);
        } else { // 3
            int b = (int)(blockIdx.y >> 5);
            int srow = (int)(blockIdx.y * 128) & (SQ - 1);
            if (srow >= lenp[b] * 2) return;
        }
    }

    extern __shared__ char smem[];
    const uint32_t sb = smem_u32(smem);
    const int tid = threadIdx.x;
    const int wid = tid >> 5, lane = tid & 31;
    const int wm = wid & 1, wn = wid >> 1;     // 2 x 2 warps, 64x64 warp tile

    const size_t aoff = (size_t)blockIdx.z * sA + (size_t)(blockIdx.y * 128) * K;
    const size_t boff = (size_t)blockIdx.z * sB + (size_t)(blockIdx.x * 128) * K;
    const bf16* Abh = Ah + aoff;
    const bf16* Abl = Al + aoff;
    const bf16* Bbh = Bh + boff;
    const bf16* Bbl = Bl + boff;

    float acc[4][8][4];
#pragma unroll
    for (int i = 0; i < 4; i++)
#pragma unroll
        for (int j = 0; j < 8; j++)
#pragma unroll
            for (int q = 0; q < 4; q++) acc[i][j][q] = 0.f;

    // cp.async: thread covers rows r0+{0,32,64,96}, 16B lane c0
    const int r0 = tid >> 2;             // 0..31
    const int c0 = tid & 3;              // 16B lane 0..3

    // ldmatrix coords
    const int rA = lane & 15, cA16 = lane >> 4;          // A x4: c16 base 0/1
    const int rB = (lane & 7) + ((lane >> 4) * 8);       // B x4 (2 n-frags)
    const int cB16 = (lane >> 3) & 1;

#define LOAD_CHUNK(stg, ko)                                                     \
    do {                                                                        \
        uint32_t dst0 = sb + (stg) * STAGEB;                                    \
        int kk = (ko) * 32;                                                     \
        _Pragma("unroll")                                                       \
        for (int i = 0; i < 4; i++) {                                           \
            int r = r0 + i * 32;                                                \
            uint32_t d = dst0 + sw64(r, c0);                                    \
            const size_t go = (size_t)r * K + kk + c0 * 8;                      \
            cp16(d,             Abh + go);                                      \
            cp16(d + TILEB,     Abl + go);                                      \
            cp16(d + 2 * TILEB, Bbh + go);                                      \
            cp16(d + 3 * TILEB, Bbl + go);                                      \
        }                                                                       \
    } while (0)

    // prologue: 2 chunks in flight
    LOAD_CHUNK(0, 0);
    CP_COMMIT();
    if (1 < nch) LOAD_CHUNK(1, 1);
    CP_COMMIT();

    for (int ch = 0; ch < nch; ch++) {
        CP_WAIT1();          // group ch complete (<=1 outstanding)
        __syncthreads();     // everyone done with stage (ch+2)%3 from iter ch-1

        int nx = ch + 2;
        if (nx < nch) LOAD_CHUNK(nx % 3, nx);
        CP_COMMIT();

        const uint32_t st = sb + (ch % 3) * STAGEB;

#pragma unroll
        for (int ks = 0; ks < 2; ks++) {
            uint32_t ah[4][4], al[4][4];
#pragma unroll
            for (int mf = 0; mf < 4; mf++) {
                int row = wm * 64 + rA + 16 * mf;
                uint32_t a_ = st + sw64(row, cA16 + 2 * ks);
                ldm4(ah[mf], a_);
                ldm4(al[mf], a_ + TILEB);
            }
#pragma unroll
            for (int jj = 0; jj < 4; jj++) {
                int row = wn * 64 + rB + 16 * jj;
                uint32_t b_ = st + 2 * TILEB + sw64(row, cB16 + 2 * ks);
                uint32_t bh[4], bl[4];
                ldm4(bh, b_);
                ldm4(bl, b_ + TILEB);
#pragma unroll
                for (int mf = 0; mf < 4; mf++) {
                    mma16816(acc[mf][2 * jj],     ah[mf], &bh[0]);   // hi*hi
                    mma16816(acc[mf][2 * jj + 1], ah[mf], &bh[2]);
                    mma16816(acc[mf][2 * jj],     ah[mf], &bl[0]);   // hi*lo
                    mma16816(acc[mf][2 * jj + 1], ah[mf], &bl[2]);
                    mma16816(acc[mf][2 * jj],     al[mf], &bh[0]);   // lo*hi
                    mma16816(acc[mf][2 * jj + 1], al[mf], &bh[2]);
                }
            }
        }
    }

    // ---------------- epilogue ----------------
    const size_t coff = (size_t)blockIdx.z * sC;
#pragma unroll
    for (int mf = 0; mf < 4; mf++) {
#pragma unroll
        for (int nf = 0; nf < 8; nf++) {
            int row = blockIdx.y * 128 + wm * 64 + mf * 16 + (lane >> 2);
            int col = blockIdx.x * 128 + wn * 64 + nf * 8 + (lane & 3) * 2;
            float* a4 = acc[mf][nf];
            if (Cf) {
                *(float2*)(Cf + coff + (size_t)row * ldc + col)       = make_float2(a4[0], a4[1]);
                *(float2*)(Cf + coff + (size_t)(row + 8) * ldc + col) = make_float2(a4[2], a4[3]);
            }
            if (Ch) {
                bf16 h0 = __float2bfloat16_rn(a4[0]);
                bf16 h1 = __float2bfloat16_rn(a4[1]);
                bf16 h2 = __float2bfloat16_rn(a4[2]);
                bf16 h3 = __float2bfloat16_rn(a4[3]);
                bf16 l0 = __float2bfloat16_rn(a4[0] - __bfloat162float(h0));
                bf16 l1 = __float2bfloat16_rn(a4[1] - __bfloat162float(h1));
                bf16 l2 = __float2bfloat16_rn(a4[2] - __bfloat162float(h2));
                bf16 l3 = __float2bfloat16_rn(a4[3] - __bfloat162float(h3));
                size_t o0 = coff + (size_t)row * ldc + col;
                size_t o1 = coff + (size_t)(row + 8) * ldc + col;
                *(bf162*)(Ch + o0) = bf162(h0, h1);
                *(bf162*)(Ch + o1) = bf162(h2, h3);
                *(bf162*)(Cl + o0) = bf162(l0, l1);
                *(bf162*)(Cl + o1) = bf162(l2, l3);
            }
        }
    }
}

// ---------------- elementwise fp32 -> hi/lo bf16 split ----------------
__global__ __launch_bounds__(256)
void split_f32(const float4* __restrict__ src, bf162* __restrict__ h,
               bf162* __restrict__ l, size_t n4)
{
    size_t i = (size_t)blockIdx.x * blockDim.x + threadIdx.x;
    if (i >= n4) return;
    float4 v = src[i];
    bf16 h0 = __float2bfloat16_rn(v.x), h1 = __float2bfloat16_rn(v.y);
    bf16 h2 = __float2bfloat16_rn(v.z), h3 = __float2bfloat16_rn(v.w);
    h[2 * i]     = bf162(h0, h1);
    h[2 * i + 1] = bf162(h2, h3);
    l[2 * i]     = bf162(__float2bfloat16_rn(v.x - __bfloat162float(h0)),
                         __float2bfloat16_rn(v.y - __bfloat162float(h1)));
    l[2 * i + 1] = bf162(__float2bfloat16_rn(v.z - __bfloat162float(h2)),
                         __float2bfloat16_rn(v.w - __bfloat162float(h3)));
}

// ---------------- V transpose + split ----------------
__global__ __launch_bounds__(256)
void transpose_split(const float* __restrict__ V, bf16* __restrict__ Th,
                     bf16* __restrict__ Tl)
{
    __shared__ float t[32][33];
    int b = blockIdx.z;
    int s0 = blockIdx.x * 32, d0 = blockIdx.y * 32;
    const float* Vb = V + (size_t)b * SQ * DH;
    int x = threadIdx.x, y = threadIdx.y;
#pragma unroll
    for (int i = 0; i < 32; i += 8)
        t[y + i][x] = Vb[(size_t)(s0 + y + i) * DH + d0 + x];
    __syncthreads();
    bf16* Thb = Th + (size_t)b * DH * SQ;
    bf16* Tlb = Tl + (size_t)b * DH * SQ;
#pragma unroll
    for (int i = 0; i < 32; i += 8) {
        float v = t[x][y + i];
        bf16 hv = __float2bfloat16_rn(v);
        size_t o = (size_t)(d0 + y + i) * SQ + s0 + x;
        Thb[o] = hv;
        Tlb[o] = __float2bfloat16_rn(v - __bfloat162float(hv));
    }
}

// ---------------- masked softmax ----------------
__global__ __launch_bounds__(256)
void softmax_mask(const float* __restrict__ P, bf16* __restrict__ Ph,
                  bf16* __restrict__ Pl, const int* __restrict__ length)
{
    int row = blockIdx.x;
    int b = row >> 12;
    const float4* p4 = (const float4*)(P + (size_t)row * SQ);
    int valid = length[b] * 2;
    int limit = (valid + 31) & ~31;   // PV reads only k < limit
    int t = threadIdx.x;

    float4 v[4];
    float e[16];
#pragma unroll
    for (int i = 0; i < 4; i++) v[i] = p4[i * 256 + t];

    float m = -INFINITY;
#pragma unroll
    for (int i = 0; i < 4; i++) {
        int k = (i * 256 + t) * 4;
        if (k + 0 < valid) m = fmaxf(m, v[i].x);
        if (k + 1 < valid) m = fmaxf(m, v[i].y);
        if (k + 2 < valid) m = fmaxf(m, v[i].z);
        if (k + 3 < valid) m = fmaxf(m, v[i].w);
    }
#pragma unroll
    for (int o = 16; o > 0; o >>= 1) m = fmaxf(m, __shfl_xor_sync(~0u, m, o));
    __shared__ float red[8];
    if ((t & 31) == 0) red[t >> 5] = m;
    __syncthreads();
    if (t < 8) {
        float q = red[t];
#pragma unroll
        for (int o = 4; o > 0; o >>= 1) q = fmaxf(q, __shfl_xor_sync(0xFFu, q, o));
        red[t] = q;
    }
    __syncthreads();
    float mx = red[0];
    __syncthreads();

    float s = 0.f;
#pragma unroll
    for (int i = 0; i < 4; i++) {
        int k = (i * 256 + t) * 4;
        e[4 * i + 0] = (k + 0 < valid) ? __expf(v[i].x - mx) : 0.f;
        e[4 * i + 1] = (k + 1 < valid) ? __expf(v[i].y - mx) : 0.f;
        e[4 * i + 2] = (k + 2 < valid) ? __expf(v[i].z - mx) : 0.f;
        e[4 * i + 3] = (k + 3 < valid) ? __expf(v[i].w - mx) : 0.f;
        s += e[4 * i] + e[4 * i + 1] + e[4 * i + 2] + e[4 * i + 3];
    }
#pragma unroll
    for (int o = 16; o > 0; o >>= 1) s += __shfl_xor_sync(~0u, s, o);
    __shared__ float red2[8];
    if ((t & 31) == 0) red2[t >> 5] = s;
    __syncthreads();
    if (t < 8) {
        float q = red2[t];
#pragma unroll
        for (int o = 4; o > 0; o >>= 1) q += __shfl_xor_sync(0xFFu, q, o);
        red2[t] = q;
    }
    __syncthreads();
    float inv = 1.0f / red2[0];

    bf162* ph = (bf162*)(Ph + (size_t)row * SQ);
    bf162* pl = (bf162*)(Pl + (size_t)row * SQ);
#pragma unroll
    for (int i = 0; i < 4; i++) {
#pragma unroll
        for (int j = 0; j < 2; j++) {
            int k = (i * 256 + t) * 4 + 2 * j;
            if (k >= limit) continue;
            float a = e[4 * i + 2 * j] * inv, c = e[4 * i + 2 * j + 1] * inv;
            bf16 ha = __float2bfloat16_rn(a), hc = __float2bfloat16_rn(c);
            bf16 la = __float2bfloat16_rn(a - __bfloat162float(ha));
            bf16 lc = __float2bfloat16_rn(c - __bfloat162float(hc));
            int o = (i * 256 + t) * 2 + j;
            ph[o] = bf162(ha, hc);
            pl[o] = bf162(la, lc);
        }
    }
}

// ---------------- host launcher ----------------
extern "C" void kernel_launch(void* const* d_in, const int* in_sizes, int n_in,
                              void* d_out, int out_size)
{
    const float* x   = (const float*)d_in[0];
    const int*   len = (const int*)d_in[1];
    const float* Wq  = (const float*)d_in[2];
    const float* Wk  = (const float*)d_in[3];
    const float* Wv  = (const float*)d_in[4];
    float* out = (float*)d_out;

    bf16 *xh, *xl, *wqh, *wql, *wkh, *wkl, *wvh, *wvl;
    bf16 *qh, *ql, *kh, *kl, *vth, *vtl, *ph, *pl;
    float *gv, *gp;
    cudaGetSymbolAddress((void**)&xh, g_Xh);   cudaGetSymbolAddress((void**)&xl, g_Xl);
    cudaGetSymbolAddress((void**)&wqh, g_Wqh); cudaGetSymbolAddress((void**)&wql, g_Wql);
    cudaGetSymbolAddress((void**)&wkh, g_Wkh); cudaGetSymbolAddress((void**)&wkl, g_Wkl);
    cudaGetSymbolAddress((void**)&wvh, g_Wvh); cudaGetSymbolAddress((void**)&wvl, g_Wvl);
    cudaGetSymbolAddress((void**)&qh, g_Qh);   cudaGetSymbolAddress((void**)&ql, g_Ql);
    cudaGetSymbolAddress((void**)&kh, g_Kh);   cudaGetSymbolAddress((void**)&kl, g_Kl);
    cudaGetSymbolAddress((void**)&gv, g_V);
    cudaGetSymbolAddress((void**)&vth, g_Vth); cudaGetSymbolAddress((void**)&vtl, g_Vtl);
    cudaGetSymbolAddress((void**)&gp, g_P);
    cudaGetSymbolAddress((void**)&ph, g_Ph);   cudaGetSymbolAddress((void**)&pl, g_Pl);

    cudaFuncSetAttribute(gemm_bf16_3p, cudaFuncAttributeMaxDynamicSharedMemorySize, SMEM_GEMM);

    // 0) split inputs/weights
    {
        size_t n4 = (size_t)MTOT * DH / 4;
        split_f32<<<(unsigned)((n4 + 255) / 256), 256>>>((const float4*)x, (bf162*)xh, (bf162*)xl, n4);
        size_t w4 = (size_t)DH * DH / 4;
        unsigned wg = (unsigned)((w4 + 255) / 256);
        split_f32<<<wg, 256>>>((const float4*)Wq, (bf162*)wqh, (bf162*)wql, w4);
        split_f32<<<wg, 256>>>((const float4*)Wk, (bf162*)wkh, (bf162*)wkl, w4);
        split_f32<<<wg, 256>>>((const float4*)Wv, (bf162*)wvh, (bf162*)wvl, w4);
    }

    dim3 blk(NTH);

    // 1) projections: M=16384, N=1024, K=1024.  Q: full; K/V: skip rows >= valid.
    {
        dim3 g(DH / 128, MTOT / 128, 1);
        gemm_bf16_3p<<<g, blk, SMEM_GEMM>>>(xh, xl, wqh, wql, nullptr, qh, ql, DH, DH, 0, 0, 0, nullptr, 0);
        gemm_bf16_3p<<<g, blk, SMEM_GEMM>>>(xh, xl, wkh, wkl, nullptr, kh, kl, DH, DH, 0, 0, 0, len, 3);
        gemm_bf16_3p<<<g, blk, SMEM_GEMM>>>(xh, xl, wvh, wvl, gv, nullptr, nullptr, DH, DH, 0, 0, 0, len, 3);
    }

    // 2) logits: batched M=N=4096, K=1024 — exit key tiles beyond valid
    {
        dim3 g(SQ / 128, SQ / 128, BB);
        gemm_bf16_3p<<<g, blk, SMEM_GEMM>>>(qh, ql, kh, kl, gp, nullptr, nullptr, DH, SQ,
                                            (size_t)SQ * DH, (size_t)SQ * DH, (size_t)SQ * SQ, len, 1);
    }

    // 3) V -> Vt hi/lo
    {
        dim3 g(SQ / 32, DH / 32, BB);
        transpose_split<<<g, dim3(32, 8)>>>(gv, vth, vtl);
    }

    // 4) masked softmax -> P hi/lo (zeros up to round32(valid))
    softmax_mask<<<BB * SQ, 256>>>(gp, ph, pl, len);

    // 5) out = P @ V: batched M=4096, N=1024, K=4096 — clamp K-loop to valid
    {
        dim3 g(DH / 128, SQ / 128, BB);
        gemm_bf16_3p<<<g, blk, SMEM_GEMM>>>(ph, pl, vth, vtl, out, nullptr, nullptr, SQ, DH,
                                            (size_t)SQ * SQ, (size_t)DH * SQ, (size_t)SQ * DH, len, 2);
    }
}

// round 14
// speedup vs baseline: 3.4484x; 1.0503x over previous
#include <cuda_runtime.h>
#include <cuda_bf16.h>
#include <cstdint>
#include <math.h>

#define BB 4
#define SQ 4096
#define DH 1024
#define MTOT (BB * SQ)   // 16384

typedef __nv_bfloat16  bf16;
typedef __nv_bfloat162 bf162;

// ---------------- scratch planes (hi/lo bf16 split) ----------------
__device__ bf16 g_Xh[(size_t)MTOT * DH], g_Xl[(size_t)MTOT * DH];
__device__ bf16 g_Wqh[(size_t)DH * DH], g_Wql[(size_t)DH * DH];
__device__ bf16 g_Wkh[(size_t)DH * DH], g_Wkl[(size_t)DH * DH];
__device__ bf16 g_Wvh[(size_t)DH * DH], g_Wvl[(size_t)DH * DH];
__device__ bf16 g_Qh[(size_t)MTOT * DH], g_Ql[(size_t)MTOT * DH];
__device__ bf16 g_Kh[(size_t)MTOT * DH], g_Kl[(size_t)MTOT * DH];
__device__ float g_V[(size_t)MTOT * DH];
__device__ bf16 g_Vth[(size_t)MTOT * DH], g_Vtl[(size_t)MTOT * DH];
__device__ float g_P[(size_t)BB * SQ * SQ];
__device__ bf16 g_Ph[(size_t)BB * SQ * SQ], g_Pl[(size_t)BB * SQ * SQ];

// ---------------- PTX helpers ----------------
__device__ __forceinline__ uint32_t smem_u32(const void* p) {
    uint32_t a;
    asm("{ .reg .u64 t; cvta.to.shared.u64 t, %1; cvt.u32.u64 %0, t; }" : "=r"(a) : "l"(p));
    return a;
}
__device__ __forceinline__ void cp16(uint32_t dst, const void* src) {
    asm volatile("cp.async.cg.shared.global [%0], [%1], 16;" :: "r"(dst), "l"(src));
}
#define CP_COMMIT() asm volatile("cp.async.commit_group;" ::: "memory")
#define CP_WAIT1()  asm volatile("cp.async.wait_group 1;" ::: "memory")

__device__ __forceinline__ void ldm4(uint32_t* r, uint32_t a) {
    asm volatile("ldmatrix.sync.aligned.m8n8.x4.shared.b16 {%0,%1,%2,%3}, [%4];"
                 : "=r"(r[0]), "=r"(r[1]), "=r"(r[2]), "=r"(r[3]) : "r"(a));
}
__device__ __forceinline__ void mma16816(float* d, const uint32_t* a, const uint32_t* b) {
    asm volatile("mma.sync.aligned.m16n8k16.row.col.f32.bf16.bf16.f32 "
                 "{%0,%1,%2,%3}, {%4,%5,%6,%7}, {%8,%9}, {%0,%1,%2,%3};"
                 : "+f"(d[0]), "+f"(d[1]), "+f"(d[2]), "+f"(d[3])
                 : "r"(a[0]), "r"(a[1]), "r"(a[2]), "r"(a[3]), "r"(b[0]), "r"(b[1]));
}

// 64B-row swizzle: 16B-lane c (0..3) XORed with (row>>1)&3.
__device__ __forceinline__ uint32_t sw64(int row, int c16) {
    return (uint32_t)(row * 64 + ((c16 ^ ((row >> 1) & 3)) << 4));
}

// ---------------- GEMM config ----------------
#define NTH 128
#define STAGES 3
#define TILEB (128 * 64)     // 8192: one plane
#define STAGEB (4 * TILEB)   // 32768: [Ah | Al | Bh | Bl]
#define SMEM_GEMM (STAGES * STAGEB)   // 98304

__global__ void __launch_bounds__(NTH, 2) gemm_bf16_3p(
    const bf16* __restrict__ Ah, const bf16* __restrict__ Al,
    const bf16* __restrict__ Bh, const bf16* __restrict__ Bl,
    float* __restrict__ Cf, bf16* __restrict__ Ch, bf16* __restrict__ Cl,
    int K, int ldc, size_t sA, size_t sB, size_t sC,
    const int* __restrict__ lenp, int lenmode)
{
    int nch = K / 32;
    if (lenmode) {
        if (lenmode == 1) {
            int valid = lenp[blockIdx.z] * 2;
            if ((int)(blockIdx.x * 128) >= valid) return;
        } else if (lenmode == 2) {
            int valid = lenp[blockIdx.z] * 2;
            nch = min(nch, (valid + 31) >> 5);
        } else { // 3
            int b = (int)(blockIdx.y >> 5);
            int srow = (int)(blockIdx.y * 128) & (SQ - 1);
            if (srow >= lenp[b] * 2) return;
        }
    }

    extern __shared__ char smem[];
    const uint32_t sb = smem_u32(smem);
    const int tid = threadIdx.x;
    const int wid = tid >> 5, lane = tid & 31;
    const int wm = wid & 1, wn = wid >> 1;     // 2 x 2 warps, 64x64 warp tile

    const size_t aoff = (size_t)blockIdx.z * sA + (size_t)(blockIdx.y * 128) * K;
    const size_t boff = (size_t)blockIdx.z * sB + (size_t)(blockIdx.x * 128) * K;
    const bf16* Abh = Ah + aoff;
    const bf16* Abl = Al + aoff;
    const bf16* Bbh = Bh + boff;
    const bf16* Bbl = Bl + boff;

    float acc[4][8][4];
#pragma unroll
    for (int i = 0; i < 4; i++)
#pragma unroll
        for (int j = 0; j < 8; j++)
#pragma unroll
            for (int q = 0; q < 4; q++) acc[i][j][q] = 0.f;

    const int r0 = tid >> 2;             // 0..31
    const int c0 = tid & 3;              // 16B lane 0..3

    const int rA = lane & 15, cA16 = lane >> 4;
    const int rB = (lane & 7) + ((lane >> 4) * 8);
    const int cB16 = (lane >> 3) & 1;

#define LOAD_CHUNK(stg, ko)                                                     \
    do {                                                                        \
        uint32_t dst0 = sb + (stg) * STAGEB;                                    \
        int kk = (ko) * 32;                                                     \
        _Pragma("unroll")                                                       \
        for (int i = 0; i < 4; i++) {                                           \
            int r = r0 + i * 32;                                                \
            uint32_t d = dst0 + sw64(r, c0);                                    \
            const size_t go = (size_t)r * K + kk + c0 * 8;                      \
            cp16(d,             Abh + go);                                      \
            cp16(d + TILEB,     Abl + go);                                      \
            cp16(d + 2 * TILEB, Bbh + go);                                      \
            cp16(d + 3 * TILEB, Bbl + go);                                      \
        }                                                                       \
    } while (0)

    LOAD_CHUNK(0, 0);
    CP_COMMIT();
    if (1 < nch) LOAD_CHUNK(1, 1);
    CP_COMMIT();

    for (int ch = 0; ch < nch; ch++) {
        CP_WAIT1();
        __syncthreads();

        int nx = ch + 2;
        if (nx < nch) LOAD_CHUNK(nx % 3, nx);
        CP_COMMIT();

        const uint32_t st = sb + (ch % 3) * STAGEB;

#pragma unroll
        for (int ks = 0; ks < 2; ks++) {
            uint32_t ah[4][4], al[4][4];
#pragma unroll
            for (int mf = 0; mf < 4; mf++) {
                int row = wm * 64 + rA + 16 * mf;
                uint32_t a_ = st + sw64(row, cA16 + 2 * ks);
                ldm4(ah[mf], a_);
                ldm4(al[mf], a_ + TILEB);
            }
#pragma unroll
            for (int jj = 0; jj < 4; jj++) {
                int row = wn * 64 + rB + 16 * jj;
                uint32_t b_ = st + 2 * TILEB + sw64(row, cB16 + 2 * ks);
                uint32_t bh[4], bl[4];
                ldm4(bh, b_);
                ldm4(bl, b_ + TILEB);
#pragma unroll
                for (int mf = 0; mf < 4; mf++) {
                    mma16816(acc[mf][2 * jj],     ah[mf], &bh[0]);   // hi*hi
                    mma16816(acc[mf][2 * jj + 1], ah[mf], &bh[2]);
                    mma16816(acc[mf][2 * jj],     ah[mf], &bl[0]);   // hi*lo
                    mma16816(acc[mf][2 * jj + 1], ah[mf], &bl[2]);
                    mma16816(acc[mf][2 * jj],     al[mf], &bh[0]);   // lo*hi
                    mma16816(acc[mf][2 * jj + 1], al[mf], &bh[2]);
                }
            }
        }
    }

    // ---------------- epilogue ----------------
    const size_t coff = (size_t)blockIdx.z * sC;
#pragma unroll
    for (int mf = 0; mf < 4; mf++) {
#pragma unroll
        for (int nf = 0; nf < 8; nf++) {
            int row = blockIdx.y * 128 + wm * 64 + mf * 16 + (lane >> 2);
            int col = blockIdx.x * 128 + wn * 64 + nf * 8 + (lane & 3) * 2;
            float* a4 = acc[mf][nf];
            if (Cf) {
                *(float2*)(Cf + coff + (size_t)row * ldc + col)       = make_float2(a4[0], a4[1]);
                *(float2*)(Cf + coff + (size_t)(row + 8) * ldc + col) = make_float2(a4[2], a4[3]);
            }
            if (Ch) {
                bf16 h0 = __float2bfloat16_rn(a4[0]);
                bf16 h1 = __float2bfloat16_rn(a4[1]);
                bf16 h2 = __float2bfloat16_rn(a4[2]);
                bf16 h3 = __float2bfloat16_rn(a4[3]);
                bf16 l0 = __float2bfloat16_rn(a4[0] - __bfloat162float(h0));
                bf16 l1 = __float2bfloat16_rn(a4[1] - __bfloat162float(h1));
                bf16 l2 = __float2bfloat16_rn(a4[2] - __bfloat162float(h2));
                bf16 l3 = __float2bfloat16_rn(a4[3] - __bfloat162float(h3));
                size_t o0 = coff + (size_t)row * ldc + col;
                size_t o1 = coff + (size_t)(row + 8) * ldc + col;
                *(bf162*)(Ch + o0) = bf162(h0, h1);
                *(bf162*)(Ch + o1) = bf162(h2, h3);
                *(bf162*)(Cl + o0) = bf162(l0, l1);
                *(bf162*)(Cl + o1) = bf162(l2, l3);
            }
        }
    }
}

// ---------------- elementwise fp32 -> hi/lo bf16 split ----------------
__global__ __launch_bounds__(256)
void split_f32(const float4* __restrict__ src, bf162* __restrict__ h,
               bf162* __restrict__ l, size_t n4)
{
    size_t i = (size_t)blockIdx.x * blockDim.x + threadIdx.x;
    if (i >= n4) return;
    float4 v = src[i];
    bf16 h0 = __float2bfloat16_rn(v.x), h1 = __float2bfloat16_rn(v.y);
    bf16 h2 = __float2bfloat16_rn(v.z), h3 = __float2bfloat16_rn(v.w);
    h[2 * i]     = bf162(h0, h1);
    h[2 * i + 1] = bf162(h2, h3);
    l[2 * i]     = bf162(__float2bfloat16_rn(v.x - __bfloat162float(h0)),
                         __float2bfloat16_rn(v.y - __bfloat162float(h1)));
    l[2 * i + 1] = bf162(__float2bfloat16_rn(v.z - __bfloat162float(h2)),
                         __float2bfloat16_rn(v.w - __bfloat162float(h3)));
}

// ---------------- V transpose + split ----------------
__global__ __launch_bounds__(256)
void transpose_split(const float* __restrict__ V, bf16* __restrict__ Th,
                     bf16* __restrict__ Tl)
{
    __shared__ float t[32][33];
    int b = blockIdx.z;
    int s0 = blockIdx.x * 32, d0 = blockIdx.y * 32;
    const float* Vb = V + (size_t)b * SQ * DH;
    int x = threadIdx.x, y = threadIdx.y;
#pragma unroll
    for (int i = 0; i < 32; i += 8)
        t[y + i][x] = Vb[(size_t)(s0 + y + i) * DH + d0 + x];
    __syncthreads();
    bf16* Thb = Th + (size_t)b * DH * SQ;
    bf16* Tlb = Tl + (size_t)b * DH * SQ;
#pragma unroll
    for (int i = 0; i < 32; i += 8) {
        float v = t[x][y + i];
        bf16 hv = __float2bfloat16_rn(v);
        size_t o = (size_t)(d0 + y + i) * SQ + s0 + x;
        Thb[o] = hv;
        Tlb[o] = __float2bfloat16_rn(v - __bfloat162float(hv));
    }
}

// ---------------- masked softmax ----------------
__global__ __launch_bounds__(256)
void softmax_mask(const float* __restrict__ P, bf16* __restrict__ Ph,
                  bf16* __restrict__ Pl, const int* __restrict__ length)
{
    int row = blockIdx.x;
    int b = row >> 12;
    const float4* p4 = (const float4*)(P + (size_t)row * SQ);
    int valid = length[b] * 2;
    int limit = (valid + 31) & ~31;   // PV reads only k < limit
    int t = threadIdx.x;

    float4 v[4];
    float e[16];
#pragma unroll
    for (int i = 0; i < 4; i++) {
        int k0 = (i * 256 + t) * 4;
        v[i] = (k0 < valid) ? p4[i * 256 + t] : make_float4(0.f, 0.f, 0.f, 0.f);
    }

    float m = -INFINITY;
#pragma unroll
    for (int i = 0; i < 4; i++) {
        int k = (i * 256 + t) * 4;
        if (k + 0 < valid) m = fmaxf(m, v[i].x);
        if (k + 1 < valid) m = fmaxf(m, v[i].y);
        if (k + 2 < valid) m = fmaxf(m, v[i].z);
        if (k + 3 < valid) m = fmaxf(m, v[i].w);
    }
#pragma unroll
    for (int o = 16; o > 0; o >>= 1) m = fmaxf(m, __shfl_xor_sync(~0u, m, o));
    __shared__ float red[8];
    if ((t & 31) == 0) red[t >> 5] = m;
    __syncthreads();
    if (t < 8) {
        float q = red[t];
#pragma unroll
        for (int o = 4; o > 0; o >>= 1) q = fmaxf(q, __shfl_xor_sync(0xFFu, q, o));
        red[t] = q;
    }
    __syncthreads();
    float mx = red[0];
    __syncthreads();

    float s = 0.f;
#pragma unroll
    for (int i = 0; i < 4; i++) {
        int k = (i * 256 + t) * 4;
        e[4 * i + 0] = (k + 0 < valid) ? __expf(v[i].x - mx) : 0.f;
        e[4 * i + 1] = (k + 1 < valid) ? __expf(v[i].y - mx) : 0.f;
        e[4 * i + 2] = (k + 2 < valid) ? __expf(v[i].z - mx) : 0.f;
        e[4 * i + 3] = (k + 3 < valid) ? __expf(v[i].w - mx) : 0.f;
        s += e[4 * i] + e[4 * i + 1] + e[4 * i + 2] + e[4 * i + 3];
    }
#pragma unroll
    for (int o = 16; o > 0; o >>= 1) s += __shfl_xor_sync(~0u, s, o);
    __shared__ float red2[8];
    if ((t & 31) == 0) red2[t >> 5] = s;
    __syncthreads();
    if (t < 8) {
        float q = red2[t];
#pragma unroll
        for (int o = 4; o > 0; o >>= 1) q += __shfl_xor_sync(0xFFu, q, o);
        red2[t] = q;
    }
    __syncthreads();
    float inv = 1.0f / red2[0];

    bf162* ph = (bf162*)(Ph + (size_t)row * SQ);
    bf162* pl = (bf162*)(Pl + (size_t)row * SQ);
#pragma unroll
    for (int i = 0; i < 4; i++) {
#pragma unroll
        for (int j = 0; j < 2; j++) {
            int k = (i * 256 + t) * 4 + 2 * j;
            if (k >= limit) continue;
            float a = e[4 * i + 2 * j] * inv, c = e[4 * i + 2 * j + 1] * inv;
            bf16 ha = __float2bfloat16_rn(a), hc = __float2bfloat16_rn(c);
            bf16 la = __float2bfloat16_rn(a - __bfloat162float(ha));
            bf16 lc = __float2bfloat16_rn(c - __bfloat162float(hc));
            int o = (i * 256 + t) * 2 + j;
            ph[o] = bf162(ha, hc);
            pl[o] = bf162(la, lc);
        }
    }
}

// ---------------- host launcher (multi-stream graph) ----------------
extern "C" void kernel_launch(void* const* d_in, const int* in_sizes, int n_in,
                              void* d_out, int out_size)
{
    const float* x   = (const float*)d_in[0];
    const int*   len = (const int*)d_in[1];
    const float* Wq  = (const float*)d_in[2];
    const float* Wk  = (const float*)d_in[3];
    const float* Wv  = (const float*)d_in[4];
    float* out = (float*)d_out;

    bf16 *xh, *xl, *wqh, *wql, *wkh, *wkl, *wvh, *wvl;
    bf16 *qh, *ql, *kh, *kl, *vth, *vtl, *ph, *pl;
    float *gv, *gp;
    cudaGetSymbolAddress((void**)&xh, g_Xh);   cudaGetSymbolAddress((void**)&xl, g_Xl);
    cudaGetSymbolAddress((void**)&wqh, g_Wqh); cudaGetSymbolAddress((void**)&wql, g_Wql);
    cudaGetSymbolAddress((void**)&wkh, g_Wkh); cudaGetSymbolAddress((void**)&wkl, g_Wkl);
    cudaGetSymbolAddress((void**)&wvh, g_Wvh); cudaGetSymbolAddress((void**)&wvl, g_Wvl);
    cudaGetSymbolAddress((void**)&qh, g_Qh);   cudaGetSymbolAddress((void**)&ql, g_Ql);
    cudaGetSymbolAddress((void**)&kh, g_Kh);   cudaGetSymbolAddress((void**)&kl, g_Kl);
    cudaGetSymbolAddress((void**)&gv, g_V);
    cudaGetSymbolAddress((void**)&vth, g_Vth); cudaGetSymbolAddress((void**)&vtl, g_Vtl);
    cudaGetSymbolAddress((void**)&gp, g_P);
    cudaGetSymbolAddress((void**)&ph, g_Ph);   cudaGetSymbolAddress((void**)&pl, g_Pl);

    cudaFuncSetAttribute(gemm_bf16_3p, cudaFuncAttributeMaxDynamicSharedMemorySize, SMEM_GEMM);

    // lazily created side streams/events (host-side objects only; created on
    // the first, uncaptured call and reused — no device memory involved)
    static cudaStream_t s1 = nullptr, s2 = nullptr;
    static cudaEvent_t eX = nullptr, eK = nullptr, eV = nullptr;
    if (!s1) {
        cudaStreamCreateWithFlags(&s1, cudaStreamNonBlocking);
        cudaStreamCreateWithFlags(&s2, cudaStreamNonBlocking);
        cudaEventCreateWithFlags(&eX, cudaEventDisableTiming);
        cudaEventCreateWithFlags(&eK, cudaEventDisableTiming);
        cudaEventCreateWithFlags(&eV, cudaEventDisableTiming);
    }
    cudaStream_t D = 0;   // capture-origin (legacy default) stream

    dim3 blk(NTH);
    size_t n4 = (size_t)MTOT * DH / 4;
    size_t w4 = (size_t)DH * DH / 4;
    unsigned wg = (unsigned)((w4 + 255) / 256);

    // D: split X (everything depends on it)
    split_f32<<<(unsigned)((n4 + 255) / 256), 256, 0, D>>>((const float4*)x, (bf162*)xh, (bf162*)xl, n4);
    cudaEventRecord(eX, D);

    // s1: K chain;  s2: V chain — both fork after X split
    cudaStreamWaitEvent(s1, eX, 0);
    cudaStreamWaitEvent(s2, eX, 0);

    {
        dim3 g(DH / 128, MTOT / 128, 1);

        // s1: Wk split + K projection
        split_f32<<<wg, 256, 0, s1>>>((const float4*)Wk, (bf162*)wkh, (bf162*)wkl, w4);
        gemm_bf16_3p<<<g, blk, SMEM_GEMM, s1>>>(xh, xl, wkh, wkl, nullptr, kh, kl, DH, DH, 0, 0, 0, len, 3);
        cudaEventRecord(eK, s1);

        // s2: Wv split + V projection + transpose
        split_f32<<<wg, 256, 0, s2>>>((const float4*)Wv, (bf162*)wvh, (bf162*)wvl, w4);
        gemm_bf16_3p<<<g, blk, SMEM_GEMM, s2>>>(xh, xl, wvh, wvl, gv, nullptr, nullptr, DH, DH, 0, 0, 0, len, 3);
        {
            dim3 gt(SQ / 32, DH / 32, BB);
            transpose_split<<<gt, dim3(32, 8), 0, s2>>>(gv, vth, vtl);
        }
        cudaEventRecord(eV, s2);

        // D: Wq split + Q projection
        split_f32<<<wg, 256, 0, D>>>((const float4*)Wq, (bf162*)wqh, (bf162*)wql, w4);
        gemm_bf16_3p<<<g, blk, SMEM_GEMM, D>>>(xh, xl, wqh, wql, nullptr, qh, ql, DH, DH, 0, 0, 0, nullptr, 0);
    }

    // D: logits (needs Q on D, K from s1)
    cudaStreamWaitEvent(D, eK, 0);
    {
        dim3 g(SQ / 128, SQ / 128, BB);
        gemm_bf16_3p<<<g, blk, SMEM_GEMM, D>>>(qh, ql, kh, kl, gp, nullptr, nullptr, DH, SQ,
                                               (size_t)SQ * DH, (size_t)SQ * DH, (size_t)SQ * SQ, len, 1);
    }

    // D: softmax
    softmax_mask<<<BB * SQ, 256, 0, D>>>(gp, ph, pl, len);

    // D: PV (needs Vt from s2 and softmax on D)
    cudaStreamWaitEvent(D, eV, 0);
    {
        dim3 g(DH / 128, SQ / 128, BB);
        gemm_bf16_3p<<<g, blk, SMEM_GEMM, D>>>(ph, pl, vth, vtl, out, nullptr, nullptr, SQ, DH,
                                               (size_t)SQ * SQ, (size_t)DH * SQ, (size_t)SQ * DH, len, 2);
    }
}

// round 17
// speedup vs baseline: 3.5182x; 1.0202x over previous
#include <cuda_runtime.h>
#include <cuda_bf16.h>
#include <cstdint>
#include <math.h>

#define BB 4
#define SQ 4096
#define DH 1024
#define MTOT (BB * SQ)   // 16384

typedef __nv_bfloat16  bf16;
typedef __nv_bfloat162 bf162;

// ---------------- scratch planes (hi/lo bf16 split) ----------------
__device__ bf16 g_Xh[(size_t)MTOT * DH], g_Xl[(size_t)MTOT * DH];
__device__ bf16 g_Wqh[(size_t)DH * DH], g_Wql[(size_t)DH * DH];
__device__ bf16 g_Wkh[(size_t)DH * DH], g_Wkl[(size_t)DH * DH];
__device__ bf16 g_Wvh[(size_t)DH * DH], g_Wvl[(size_t)DH * DH];
__device__ bf16 g_Qh[(size_t)MTOT * DH], g_Ql[(size_t)MTOT * DH];
__device__ bf16 g_Kh[(size_t)MTOT * DH], g_Kl[(size_t)MTOT * DH];
__device__ float g_V[(size_t)MTOT * DH];
__device__ bf16 g_Vth[(size_t)MTOT * DH], g_Vtl[(size_t)MTOT * DH];
__device__ float g_P[(size_t)BB * SQ * SQ];
__device__ bf16 g_Ph[(size_t)BB * SQ * SQ], g_Pl[(size_t)BB * SQ * SQ];

// ---------------- PTX helpers ----------------
__device__ __forceinline__ uint32_t smem_u32(const void* p) {
    uint32_t a;
    asm("{ .reg .u64 t; cvta.to.shared.u64 t, %1; cvt.u32.u64 %0, t; }" : "=r"(a) : "l"(p));
    return a;
}
__device__ __forceinline__ void cp16(uint32_t dst, const void* src) {
    asm volatile("cp.async.cg.shared.global [%0], [%1], 16;" :: "r"(dst), "l"(src));
}
#define CP_COMMIT() asm volatile("cp.async.commit_group;" ::: "memory")
#define CP_WAIT1()  asm volatile("cp.async.wait_group 1;" ::: "memory")

__device__ __forceinline__ void ldm4(uint32_t* r, uint32_t a) {
    asm volatile("ldmatrix.sync.aligned.m8n8.x4.shared.b16 {%0,%1,%2,%3}, [%4];"
                 : "=r"(r[0]), "=r"(r[1]), "=r"(r[2]), "=r"(r[3]) : "r"(a));
}
__device__ __forceinline__ void mma16816(float* d, const uint32_t* a, const uint32_t* b) {
    asm volatile("mma.sync.aligned.m16n8k16.row.col.f32.bf16.bf16.f32 "
                 "{%0,%1,%2,%3}, {%4,%5,%6,%7}, {%8,%9}, {%0,%1,%2,%3};"
                 : "+f"(d[0]), "+f"(d[1]), "+f"(d[2]), "+f"(d[3])
                 : "r"(a[0]), "r"(a[1]), "r"(a[2]), "r"(a[3]), "r"(b[0]), "r"(b[1]));
}

// 64B-row swizzle: 16B-lane c (0..3) XORed with (row>>1)&3.
__device__ __forceinline__ uint32_t sw64(int row, int c16) {
    return (uint32_t)(row * 64 + ((c16 ^ ((row >> 1) & 3)) << 4));
}

// ---------------- GEMM config ----------------
#define NTH 128
#define STAGES 3
#define TILEB (128 * 64)     // 8192: one plane
#define STAGEB (4 * TILEB)   // 32768: [Ah | Al | Bh | Bl]
#define SMEM_GEMM (STAGES * STAGEB)   // 98304

__global__ void __launch_bounds__(NTH, 2) gemm_bf16_3p(
    const bf16* __restrict__ Ah, const bf16* __restrict__ Al,
    const bf16* __restrict__ Bh, const bf16* __restrict__ Bl,
    float* __restrict__ Cf, bf16* __restrict__ Ch, bf16* __restrict__ Cl,
    int K, int ldc, size_t sA, size_t sB, size_t sC,
    const int* __restrict__ lenp, int lenmode)
{
    int nch = K / 32;
    if (lenmode) {
        if (lenmode == 1) {
            int valid = lenp[blockIdx.z] * 2;
            if ((int)(blockIdx.x * 128) >= valid) return;
        } else if (lenmode == 2) {
            int valid = lenp[blockIdx.z] * 2;
            nch = min(nch, (valid + 31) >> 5);
        } else { // 3
            int b = (int)(blockIdx.y >> 5);
            int srow = (int)(blockIdx.y * 128) & (SQ - 1);
            if (srow >= lenp[b] * 2) return;
        }
    }

    extern __shared__ char smem[];
    const uint32_t sb = smem_u32(smem);
    const int tid = threadIdx.x;
    const int wid = tid >> 5, lane = tid & 31;
    const int wm = wid & 1, wn = wid >> 1;     // 2 x 2 warps, 64x64 warp tile

    const size_t aoff = (size_t)blockIdx.z * sA + (size_t)(blockIdx.y * 128) * K;
    const size_t boff = (size_t)blockIdx.z * sB + (size_t)(blockIdx.x * 128) * K;
    const bf16* Abh = Ah + aoff;
    const bf16* Abl = Al + aoff;
    const bf16* Bbh = Bh + boff;
    const bf16* Bbl = Bl + boff;

    float acc[4][8][4];
#pragma unroll
    for (int i = 0; i < 4; i++)
#pragma unroll
        for (int j = 0; j < 8; j++)
#pragma unroll
            for (int q = 0; q < 4; q++) acc[i][j][q] = 0.f;

    const int r0 = tid >> 2;             // 0..31
    const int c0 = tid & 3;              // 16B lane 0..3

    const int rA = lane & 15, cA16 = lane >> 4;
    const int rB = (lane & 7) + ((lane >> 4) * 8);
    const int cB16 = (lane >> 3) & 1;

#define LOAD_CHUNK(stg, ko)                                                     \
    do {                                                                        \
        uint32_t dst0 = sb + (stg) * STAGEB;                                    \
        int kk = (ko) * 32;                                                     \
        _Pragma("unroll")                                                       \
        for (int i = 0; i < 4; i++) {                                           \
            int r = r0 + i * 32;                                                \
            uint32_t d = dst0 + sw64(r, c0);                                    \
            const size_t go = (size_t)r * K + kk + c0 * 8;                      \
            cp16(d,             Abh + go);                                      \
            cp16(d + TILEB,     Abl + go);                                      \
            cp16(d + 2 * TILEB, Bbh + go);                                      \
            cp16(d + 3 * TILEB, Bbl + go);                                      \
        }                                                                       \
    } while (0)

    LOAD_CHUNK(0, 0);
    CP_COMMIT();
    if (1 < nch) LOAD_CHUNK(1, 1);
    CP_COMMIT();

    for (int ch = 0; ch < nch; ch++) {
        CP_WAIT1();
        __syncthreads();

        int nx = ch + 2;
        if (nx < nch) LOAD_CHUNK(nx % 3, nx);
        CP_COMMIT();

        const uint32_t st = sb + (ch % 3) * STAGEB;

#pragma unroll
        for (int ks = 0; ks < 2; ks++) {
            uint32_t ah[4][4], al[4][4];
#pragma unroll
            for (int mf = 0; mf < 4; mf++) {
                int row = wm * 64 + rA + 16 * mf;
                uint32_t a_ = st + sw64(row, cA16 + 2 * ks);
                ldm4(ah[mf], a_);
                ldm4(al[mf], a_ + TILEB);
            }
#pragma unroll
            for (int jj = 0; jj < 4; jj++) {
                int row = wn * 64 + rB + 16 * jj;
                uint32_t b_ = st + 2 * TILEB + sw64(row, cB16 + 2 * ks);
                uint32_t bh[4], bl[4];
                ldm4(bh, b_);
                ldm4(bl, b_ + TILEB);
#pragma unroll
                for (int mf = 0; mf < 4; mf++) {
                    mma16816(acc[mf][2 * jj],     ah[mf], &bh[0]);   // hi*hi
                    mma16816(acc[mf][2 * jj + 1], ah[mf], &bh[2]);
                    mma16816(acc[mf][2 * jj],     ah[mf], &bl[0]);   // hi*lo
                    mma16816(acc[mf][2 * jj + 1], ah[mf], &bl[2]);
                    mma16816(acc[mf][2 * jj],     al[mf], &bh[0]);   // lo*hi
                    mma16816(acc[mf][2 * jj + 1], al[mf], &bh[2]);
                }
            }
        }
    }

    // ---------------- epilogue ----------------
    const size_t coff = (size_t)blockIdx.z * sC;
#pragma unroll
    for (int mf = 0; mf < 4; mf++) {
#pragma unroll
        for (int nf = 0; nf < 8; nf++) {
            int row = blockIdx.y * 128 + wm * 64 + mf * 16 + (lane >> 2);
            int col = blockIdx.x * 128 + wn * 64 + nf * 8 + (lane & 3) * 2;
            float* a4 = acc[mf][nf];
            if (Cf) {
                *(float2*)(Cf + coff + (size_t)row * ldc + col)       = make_float2(a4[0], a4[1]);
                *(float2*)(Cf + coff + (size_t)(row + 8) * ldc + col) = make_float2(a4[2], a4[3]);
            }
            if (Ch) {
                bf16 h0 = __float2bfloat16_rn(a4[0]);
                bf16 h1 = __float2bfloat16_rn(a4[1]);
                bf16 h2 = __float2bfloat16_rn(a4[2]);
                bf16 h3 = __float2bfloat16_rn(a4[3]);
                bf16 l0 = __float2bfloat16_rn(a4[0] - __bfloat162float(h0));
                bf16 l1 = __float2bfloat16_rn(a4[1] - __bfloat162float(h1));
                bf16 l2 = __float2bfloat16_rn(a4[2] - __bfloat162float(h2));
                bf16 l3 = __float2bfloat16_rn(a4[3] - __bfloat162float(h3));
                size_t o0 = coff + (size_t)row * ldc + col;
                size_t o1 = coff + (size_t)(row + 8) * ldc + col;
                *(bf162*)(Ch + o0) = bf162(h0, h1);
                *(bf162*)(Ch + o1) = bf162(h2, h3);
                *(bf162*)(Cl + o0) = bf162(l0, l1);
                *(bf162*)(Cl + o1) = bf162(l2, l3);
            }
        }
    }
}

// ---------------- elementwise fp32 -> hi/lo bf16 split ----------------
__global__ __launch_bounds__(256)
void split_f32(const float4* __restrict__ src, bf162* __restrict__ h,
               bf162* __restrict__ l, size_t n4)
{
    size_t i = (size_t)blockIdx.x * blockDim.x + threadIdx.x;
    if (i >= n4) return;
    float4 v = src[i];
    bf16 h0 = __float2bfloat16_rn(v.x), h1 = __float2bfloat16_rn(v.y);
    bf16 h2 = __float2bfloat16_rn(v.z), h3 = __float2bfloat16_rn(v.w);
    h[2 * i]     = bf162(h0, h1);
    h[2 * i + 1] = bf162(h2, h3);
    l[2 * i]     = bf162(__float2bfloat16_rn(v.x - __bfloat162float(h0)),
                         __float2bfloat16_rn(v.y - __bfloat162float(h1)));
    l[2 * i + 1] = bf162(__float2bfloat16_rn(v.z - __bfloat162float(h2)),
                         __float2bfloat16_rn(v.w - __bfloat162float(h3)));
}

// ---------------- V transpose + split ----------------
__global__ __launch_bounds__(256)
void transpose_split(const float* __restrict__ V, bf16* __restrict__ Th,
                     bf16* __restrict__ Tl)
{
    __shared__ float t[32][33];
    int b = blockIdx.z;
    int s0 = blockIdx.x * 32, d0 = blockIdx.y * 32;
    const float* Vb = V + (size_t)b * SQ * DH;
    int x = threadIdx.x, y = threadIdx.y;
#pragma unroll
    for (int i = 0; i < 32; i += 8)
        t[y + i][x] = Vb[(size_t)(s0 + y + i) * DH + d0 + x];
    __syncthreads();
    bf16* Thb = Th + (size_t)b * DH * SQ;
    bf16* Tlb = Tl + (size_t)b * DH * SQ;
#pragma unroll
    for (int i = 0; i < 32; i += 8) {
        float v = t[x][y + i];
        bf16 hv = __float2bfloat16_rn(v);
        size_t o = (size_t)(d0 + y + i) * SQ + s0 + x;
        Thb[o] = hv;
        Tlb[o] = __float2bfloat16_rn(v - __bfloat162float(hv));
    }
}

// ---------------- masked softmax (single batch; pointers pre-offset) ----------------
__global__ __launch_bounds__(256)
void softmax_mask(const float* __restrict__ P, bf16* __restrict__ Ph,
                  bf16* __restrict__ Pl, const int* __restrict__ length)
{
    int row = blockIdx.x;                      // 0..SQ-1 within this batch
    const float4* p4 = (const float4*)(P + (size_t)row * SQ);
    int valid = length[0] * 2;
    int limit = (valid + 31) & ~31;            // PV reads only k < limit
    int t = threadIdx.x;

    float4 v[4];
    float e[16];
#pragma unroll
    for (int i = 0; i < 4; i++) {
        int k0 = (i * 256 + t) * 4;
        v[i] = (k0 < valid) ? p4[i * 256 + t] : make_float4(0.f, 0.f, 0.f, 0.f);
    }

    float m = -INFINITY;
#pragma unroll
    for (int i = 0; i < 4; i++) {
        int k = (i * 256 + t) * 4;
        if (k + 0 < valid) m = fmaxf(m, v[i].x);
        if (k + 1 < valid) m = fmaxf(m, v[i].y);
        if (k + 2 < valid) m = fmaxf(m, v[i].z);
        if (k + 3 < valid) m = fmaxf(m, v[i].w);
    }
#pragma unroll
    for (int o = 16; o > 0; o >>= 1) m = fmaxf(m, __shfl_xor_sync(~0u, m, o));
    __shared__ float red[8];
    if ((t & 31) == 0) red[t >> 5] = m;
    __syncthreads();
    if (t < 8) {
        float q = red[t];
#pragma unroll
        for (int o = 4; o > 0; o >>= 1) q = fmaxf(q, __shfl_xor_sync(0xFFu, q, o));
        red[t] = q;
    }
    __syncthreads();
    float mx = red[0];
    __syncthreads();

    float s = 0.f;
#pragma unroll
    for (int i = 0; i < 4; i++) {
        int k = (i * 256 + t) * 4;
        e[4 * i + 0] = (k + 0 < valid) ? __expf(v[i].x - mx) : 0.f;
        e[4 * i + 1] = (k + 1 < valid) ? __expf(v[i].y - mx) : 0.f;
        e[4 * i + 2] = (k + 2 < valid) ? __expf(v[i].z - mx) : 0.f;
        e[4 * i + 3] = (k + 3 < valid) ? __expf(v[i].w - mx) : 0.f;
        s += e[4 * i] + e[4 * i + 1] + e[4 * i + 2] + e[4 * i + 3];
    }
#pragma unroll
    for (int o = 16; o > 0; o >>= 1) s += __shfl_xor_sync(~0u, s, o);
    __shared__ float red2[8];
    if ((t & 31) == 0) red2[t >> 5] = s;
    __syncthreads();
    if (t < 8) {
        float q = red2[t];
#pragma unroll
        for (int o = 4; o > 0; o >>= 1) q += __shfl_xor_sync(0xFFu, q, o);
        red2[t] = q;
    }
    __syncthreads();
    float inv = 1.0f / red2[0];

    bf162* ph = (bf162*)(Ph + (size_t)row * SQ);
    bf162* pl = (bf162*)(Pl + (size_t)row * SQ);
#pragma unroll
    for (int i = 0; i < 4; i++) {
#pragma unroll
        for (int j = 0; j < 2; j++) {
            int k = (i * 256 + t) * 4 + 2 * j;
            if (k >= limit) continue;
            float a = e[4 * i + 2 * j] * inv, c = e[4 * i + 2 * j + 1] * inv;
            bf16 ha = __float2bfloat16_rn(a), hc = __float2bfloat16_rn(c);
            bf16 la = __float2bfloat16_rn(a - __bfloat162float(ha));
            bf16 lc = __float2bfloat16_rn(c - __bfloat162float(hc));
            int o = (i * 256 + t) * 2 + j;
            ph[o] = bf162(ha, hc);
            pl[o] = bf162(la, lc);
        }
    }
}

// ---------------- host launcher (batch-pipelined, 2 side streams only) ----------------
extern "C" void kernel_launch(void* const* d_in, const int* in_sizes, int n_in,
                              void* d_out, int out_size)
{
    const float* x   = (const float*)d_in[0];
    const int*   len = (const int*)d_in[1];
    const float* Wq  = (const float*)d_in[2];
    const float* Wk  = (const float*)d_in[3];
    const float* Wv  = (const float*)d_in[4];
    float* out = (float*)d_out;

    bf16 *xh, *xl, *wqh, *wql, *wkh, *wkl, *wvh, *wvl;
    bf16 *qh, *ql, *kh, *kl, *vth, *vtl, *ph, *pl;
    float *gv, *gp;
    cudaGetSymbolAddress((void**)&xh, g_Xh);   cudaGetSymbolAddress((void**)&xl, g_Xl);
    cudaGetSymbolAddress((void**)&wqh, g_Wqh); cudaGetSymbolAddress((void**)&wql, g_Wql);
    cudaGetSymbolAddress((void**)&wkh, g_Wkh); cudaGetSymbolAddress((void**)&wkl, g_Wkl);
    cudaGetSymbolAddress((void**)&wvh, g_Wvh); cudaGetSymbolAddress((void**)&wvl, g_Wvl);
    cudaGetSymbolAddress((void**)&qh, g_Qh);   cudaGetSymbolAddress((void**)&ql, g_Ql);
    cudaGetSymbolAddress((void**)&kh, g_Kh);   cudaGetSymbolAddress((void**)&kl, g_Kl);
    cudaGetSymbolAddress((void**)&gv, g_V);
    cudaGetSymbolAddress((void**)&vth, g_Vth); cudaGetSymbolAddress((void**)&vtl, g_Vtl);
    cudaGetSymbolAddress((void**)&gp, g_P);
    cudaGetSymbolAddress((void**)&ph, g_Ph);   cudaGetSymbolAddress((void**)&pl, g_Pl);

    cudaFuncSetAttribute(gemm_bf16_3p, cudaFuncAttributeMaxDynamicSharedMemorySize, SMEM_GEMM);

    // lazily created side streams/events — SAME count as the passing R14 graph
    // (2 streams); events are host-side, timing-disabled.
    static cudaStream_t s1 = nullptr, s2 = nullptr;
    static cudaEvent_t eX = nullptr, eQ = nullptr, eK = nullptr, eV = nullptr;
    static cudaEvent_t eB1 = nullptr, eB2 = nullptr;
    if (!s1) {
        cudaStreamCreateWithFlags(&s1, cudaStreamNonBlocking);
        cudaStreamCreateWithFlags(&s2, cudaStreamNonBlocking);
        cudaEventCreateWithFlags(&eX, cudaEventDisableTiming);
        cudaEventCreateWithFlags(&eQ, cudaEventDisableTiming);
        cudaEventCreateWithFlags(&eK, cudaEventDisableTiming);
        cudaEventCreateWithFlags(&eV, cudaEventDisableTiming);
        cudaEventCreateWithFlags(&eB1, cudaEventDisableTiming);
        cudaEventCreateWithFlags(&eB2, cudaEventDisableTiming);
    }
    cudaStream_t D = 0;   // capture-origin stream

    dim3 blk(NTH);
    size_t n4 = (size_t)MTOT * DH / 4;
    size_t w4 = (size_t)DH * DH / 4;
    unsigned wg = (unsigned)((w4 + 255) / 256);

    // D: split X
    split_f32<<<(unsigned)((n4 + 255) / 256), 256, 0, D>>>((const float4*)x, (bf162*)xh, (bf162*)xl, n4);
    cudaEventRecord(eX, D);

    cudaStreamWaitEvent(s1, eX, 0);
    cudaStreamWaitEvent(s2, eX, 0);

    {
        dim3 g(DH / 128, MTOT / 128, 1);

        // s1: Wk split + K projection
        split_f32<<<wg, 256, 0, s1>>>((const float4*)Wk, (bf162*)wkh, (bf162*)wkl, w4);
        gemm_bf16_3p<<<g, blk, SMEM_GEMM, s1>>>(xh, xl, wkh, wkl, nullptr, kh, kl, DH, DH, 0, 0, 0, len, 3);
        cudaEventRecord(eK, s1);

        // s2: Wv split + V projection + transpose
        split_f32<<<wg, 256, 0, s2>>>((const float4*)Wv, (bf162*)wvh, (bf162*)wvl, w4);
        gemm_bf16_3p<<<g, blk, SMEM_GEMM, s2>>>(xh, xl, wvh, wvl, gv, nullptr, nullptr, DH, DH, 0, 0, 0, len, 3);
        {
            dim3 gt(SQ / 32, DH / 32, BB);
            transpose_split<<<gt, dim3(32, 8), 0, s2>>>(gv, vth, vtl);
        }
        cudaEventRecord(eV, s2);

        // D: Wq split + Q projection
        split_f32<<<wg, 256, 0, D>>>((const float4*)Wq, (bf162*)wqh, (bf162*)wql, w4);
        gemm_bf16_3p<<<g, blk, SMEM_GEMM, D>>>(xh, xl, wqh, wql, nullptr, qh, ql, DH, DH, 0, 0, 0, nullptr, 0);
        cudaEventRecord(eQ, D);
    }

    // Per-batch attention chains distributed across {D, s1, s2}:
    //   D: batch 0 (longest, valid=4096);  s1: batches 1,3;  s2: batch 2
    // D needs K (from s1) and Vt (from s2); s1 needs Q,Vt; s2 needs Q,K,Vt.
    cudaStreamWaitEvent(D, eK, 0);
    cudaStreamWaitEvent(D, eV, 0);
    cudaStreamWaitEvent(s1, eQ, 0);
    cudaStreamWaitEvent(s1, eV, 0);
    cudaStreamWaitEvent(s2, eQ, 0);
    cudaStreamWaitEvent(s2, eK, 0);

    const cudaStream_t chainS[BB] = {D, s1, s2, s1};
    for (int b = 0; b < BB; b++) {
        cudaStream_t S = chainS[b];
        const size_t qkOff = (size_t)b * SQ * DH;
        const size_t pOff  = (size_t)b * SQ * SQ;

        {
            dim3 g(SQ / 128, SQ / 128, 1);
            gemm_bf16_3p<<<g, blk, SMEM_GEMM, S>>>(qh + qkOff, ql + qkOff, kh + qkOff, kl + qkOff,
                                                   gp + pOff, nullptr, nullptr, DH, SQ,
                                                   0, 0, 0, len + b, 1);
        }
        softmax_mask<<<SQ, 256, 0, S>>>(gp + pOff, ph + pOff, pl + pOff, len + b);
        {
            dim3 g(DH / 128, SQ / 128, 1);
            gemm_bf16_3p<<<g, blk, SMEM_GEMM, S>>>(ph + pOff, pl + pOff, vth + qkOff, vtl + qkOff,
                                                   out + qkOff, nullptr, nullptr, SQ, DH,
                                                   0, 0, 0, len + b, 2);
        }
    }

    // rejoin side streams into the capture-origin stream
    cudaEventRecord(eB1, s1);
    cudaEventRecord(eB2, s2);
    cudaStreamWaitEvent(D, eB1, 0);
    cudaStreamWaitEvent(D, eB2, 0);
}